// round 6
// baseline (speedup 1.0000x reference)
#include <cuda_runtime.h>
#include <cstdint>

#define NMAX  100000
#define EMAX  1600000
#define DHID  128
#define PREP_BLOCKS 128
#define PREP_THREADS 1024

typedef unsigned long long u64;

// Scratch (static device globals; allocation is forbidden)
__device__ float g_dis[NMAX];
__device__ int   g_deg [NMAX];
__device__ int   g_rowptr[NMAX + 1];
__device__ int   g_cursor[NMAX];
__device__ int   g_esrc[EMAX];
__device__ float g_h  [NMAX * DHID];
__device__ float g_t  [NMAX * DHID];
__device__ int   g_bsum[PREP_BLOCKS];
__device__ int   g_boff[PREP_BLOCKS];
__device__ int   g_total;
__device__ unsigned g_bar;

// ---------------------------------------------------------------- grid sync
__device__ __forceinline__ void grid_sync(int nb) {
    __syncthreads();
    if (threadIdx.x == 0) {
        __threadfence();
        unsigned ticket = atomicAdd(&g_bar, 1u);
        unsigned phase  = ticket / (unsigned)nb + 1u;
        while (atomicAdd(&g_bar, 0u) < phase * (unsigned)nb) { }
    }
    __syncthreads();
}

// ---------------------------------------------------------------- fused prep
__global__ __launch_bounds__(PREP_THREADS, 1)
void k_prep(const int* __restrict__ src, const int* __restrict__ dst, int e, int n) {
    const int tid  = threadIdx.x;
    const int lane = tid & 31, wid = tid >> 5;
    const int T    = PREP_BLOCKS * PREP_THREADS;
    const int gtid = blockIdx.x * PREP_THREADS + tid;
    __shared__ int sh[32];
    __shared__ int s_boff;

    for (int i = gtid; i < n; i += T) g_deg[i] = 0;
    grid_sync(PREP_BLOCKS);

    for (int i = gtid; i < e; i += T) atomicAdd(&g_deg[dst[i]], 1);
    grid_sync(PREP_BLOCKS);

    for (int i = gtid; i < n; i += T) g_dis[i] = rsqrtf((float)g_deg[i] + 1.0f);

    const int per = (n + T - 1) / T;
    const int cb  = gtid * per;
    const int ce  = min(cb + per, n);
    int csum = 0;
    for (int i = cb; i < ce; i++) csum += g_deg[i];

    int x = csum;
#pragma unroll
    for (int o = 1; o < 32; o <<= 1) {
        int y = __shfl_up_sync(0xffffffffu, x, o);
        if (lane >= o) x += y;
    }
    if (lane == 31) sh[wid] = x;
    __syncthreads();
    if (wid == 0) {
        int w = sh[lane];
        int xx = w;
#pragma unroll
        for (int o = 1; o < 32; o <<= 1) {
            int y = __shfl_up_sync(0xffffffffu, xx, o);
            if (lane >= o) xx += y;
        }
        sh[lane] = xx - w;
        if (lane == 31) g_bsum[blockIdx.x] = xx;
    }
    __syncthreads();
    const int thr_excl = x - csum + sh[wid];
    grid_sync(PREP_BLOCKS);

    if (blockIdx.x == 0 && wid == 0) {
        int carry = 0;
        for (int base = 0; base < PREP_BLOCKS; base += 32) {
            int v = g_bsum[base + lane];
            int s = v;
#pragma unroll
            for (int o = 1; o < 32; o <<= 1) {
                int y = __shfl_up_sync(0xffffffffu, s, o);
                if (lane >= o) s += y;
            }
            g_boff[base + lane] = s - v + carry;
            carry += __shfl_sync(0xffffffffu, s, 31);
        }
        if (lane == 0) g_total = carry;
    }
    grid_sync(PREP_BLOCKS);

    if (tid == 0) s_boff = g_boff[blockIdx.x];
    __syncthreads();
    int run = s_boff + thr_excl;
    for (int i = cb; i < ce; i++) {
        g_rowptr[i] = run;
        g_cursor[i] = run;
        run += g_deg[i];
    }
    if (gtid == 0) g_rowptr[n] = g_total;
    grid_sync(PREP_BLOCKS);

    for (int i = gtid; i < e; i += T) {
        int pos = atomicAdd(&g_cursor[dst[i]], 1);
        g_esrc[pos] = src[i];
    }
}

__global__ void k_zero4(float* p, int n4) {
    int i = blockIdx.x * blockDim.x + threadIdx.x;
    if (i < n4) reinterpret_cast<float4*>(p)[i] = make_float4(0.f, 0.f, 0.f, 0.f);
}

// ---------------------------------------------------------------- GEMM
// Register-tiled SGEMM with packed f32x2 FMA inner loop.
// A: [M,128] row-major, W: [128,BN] row-major, out: [M,BN].
// Block tile 128xBN, thread tile 8x8 (as 8x4 f32x2 pairs), BK=16, double-buffered.
template <int BN, bool SCALE, bool BIAS>
__global__ void k_gemm(const float* __restrict__ A, const float* __restrict__ W,
                       const float* __restrict__ bias, const float* __restrict__ dis,
                       float* __restrict__ out, int M) {
    constexpr int BM = 128, BK = 16;
    constexpr int TN = BN / 8;
    constexpr int TM = BM / 8;          // 16
    constexpr int T  = TN * TM;         // 256 / 128
    constexpr int A_PER = (BM * BK / 4) / T;
    constexpr int W_PER = (BK * BN / 4) / T;
    constexpr int NKT = 128 / BK;

    __shared__ float As[2][BK][BM];
    __shared__ float Ws[2][BK][BN];

    const int tid = threadIdx.x;
    const int tn  = tid % TN;
    const int tm  = tid / TN;
    const int row0 = blockIdx.x * BM;

    u64 acc2[8][4];
#pragma unroll
    for (int i = 0; i < 8; i++)
#pragma unroll
        for (int j = 0; j < 4; j++) acc2[i][j] = 0ull;

    float4 rA[A_PER], rW[W_PER];

    // ---- prologue: load k-tile 0 ----
#pragma unroll
    for (int j = 0; j < A_PER; j++) {
        int i = tid + j * T;
        int m = i >> 2, kq = i & 3;
        int gr = row0 + m; if (gr >= M) gr = M - 1;
        rA[j] = *reinterpret_cast<const float4*>(&A[(size_t)gr * 128 + kq * 4]);
    }
#pragma unroll
    for (int j = 0; j < W_PER; j++) {
        int i = tid + j * T;
        int k = i / (BN / 4), c = i % (BN / 4);
        rW[j] = *reinterpret_cast<const float4*>(&W[(size_t)k * BN + c * 4]);
    }
#pragma unroll
    for (int j = 0; j < A_PER; j++) {
        int i = tid + j * T;
        int m = i >> 2, kq = i & 3;
        As[0][kq * 4 + 0][m] = rA[j].x;
        As[0][kq * 4 + 1][m] = rA[j].y;
        As[0][kq * 4 + 2][m] = rA[j].z;
        As[0][kq * 4 + 3][m] = rA[j].w;
    }
#pragma unroll
    for (int j = 0; j < W_PER; j++) {
        int i = tid + j * T;
        int k = i / (BN / 4), c = i % (BN / 4);
        *reinterpret_cast<float4*>(&Ws[0][k][c * 4]) = rW[j];
    }
    __syncthreads();

    int buf = 0;
    for (int kt = 0; kt < NKT; kt++) {
        if (kt < NKT - 1) {
            const int k0 = (kt + 1) * BK;
#pragma unroll
            for (int j = 0; j < A_PER; j++) {
                int i = tid + j * T;
                int m = i >> 2, kq = i & 3;
                int gr = row0 + m; if (gr >= M) gr = M - 1;
                rA[j] = *reinterpret_cast<const float4*>(&A[(size_t)gr * 128 + k0 + kq * 4]);
            }
#pragma unroll
            for (int j = 0; j < W_PER; j++) {
                int i = tid + j * T;
                int k = i / (BN / 4), c = i % (BN / 4);
                rW[j] = *reinterpret_cast<const float4*>(&W[(size_t)(k0 + k) * BN + c * 4]);
            }
        }
#pragma unroll
        for (int k = 0; k < BK; k++) {
            float a[8];
            *reinterpret_cast<float4*>(&a[0]) = *reinterpret_cast<float4*>(&As[buf][k][tm * 8 + 0]);
            *reinterpret_cast<float4*>(&a[4]) = *reinterpret_cast<float4*>(&As[buf][k][tm * 8 + 4]);
            ulonglong2 w0 = *reinterpret_cast<ulonglong2*>(&Ws[buf][k][tn * 8 + 0]);
            ulonglong2 w1 = *reinterpret_cast<ulonglong2*>(&Ws[buf][k][tn * 8 + 4]);
            u64 b2[4] = {w0.x, w0.y, w1.x, w1.y};
            u64 a2[8];
#pragma unroll
            for (int i = 0; i < 8; i++)
                asm("mov.b64 %0, {%1, %1};" : "=l"(a2[i]) : "r"(__float_as_uint(a[i])));
#pragma unroll
            for (int i = 0; i < 8; i++)
#pragma unroll
                for (int j = 0; j < 4; j++)
                    asm("fma.rn.f32x2 %0, %1, %2, %0;"
                        : "+l"(acc2[i][j]) : "l"(a2[i]), "l"(b2[j]));
        }
        if (kt < NKT - 1) {
            int nb = buf ^ 1;
#pragma unroll
            for (int j = 0; j < A_PER; j++) {
                int i = tid + j * T;
                int m = i >> 2, kq = i & 3;
                As[nb][kq * 4 + 0][m] = rA[j].x;
                As[nb][kq * 4 + 1][m] = rA[j].y;
                As[nb][kq * 4 + 2][m] = rA[j].z;
                As[nb][kq * 4 + 3][m] = rA[j].w;
            }
#pragma unroll
            for (int j = 0; j < W_PER; j++) {
                int i = tid + j * T;
                int k = i / (BN / 4), c = i % (BN / 4);
                *reinterpret_cast<float4*>(&Ws[nb][k][c * 4]) = rW[j];
            }
            __syncthreads();
            buf = nb;
        }
    }

    // ---- epilogue ----
    float bv[8];
    if (BIAS) {
        *reinterpret_cast<float4*>(&bv[0]) = *reinterpret_cast<const float4*>(&bias[tn * 8 + 0]);
        *reinterpret_cast<float4*>(&bv[4]) = *reinterpret_cast<const float4*>(&bias[tn * 8 + 4]);
    }
#pragma unroll
    for (int i = 0; i < 8; i++) {
        int gr = row0 + tm * 8 + i;
        if (gr < M) {
            float sc = SCALE ? dis[gr] : 1.0f;
#pragma unroll
            for (int j = 0; j < 8; j += 4) {
                float2 p0 = *reinterpret_cast<float2*>(&acc2[i][j / 2]);
                float2 p1 = *reinterpret_cast<float2*>(&acc2[i][j / 2 + 1]);
                float4 v;
                v.x = p0.x * sc;
                v.y = p0.y * sc;
                v.z = p1.x * sc;
                v.w = p1.y * sc;
                if (BIAS) { v.x += bv[j]; v.y += bv[j + 1]; v.z += bv[j + 2]; v.w += bv[j + 3]; }
                *reinterpret_cast<float4*>(&out[(size_t)gr * BN + tn * 8 + j]) = v;
            }
        }
    }
}

// ---------------------------------------------------------------- aggregation
template <int COLS, bool RELU>
__global__ void k_agg(const float* __restrict__ tb, const int* __restrict__ rowptr,
                      const int* __restrict__ esrc, const float* __restrict__ dis,
                      const float* __restrict__ bias, float* __restrict__ out, int n) {
    const int warp = (blockIdx.x * blockDim.x + threadIdx.x) >> 5;
    const int lane = threadIdx.x & 31;
    if (warp >= n) return;
    const int beg = __ldg(&rowptr[warp]);
    const int end = __ldg(&rowptr[warp + 1]);

    if constexpr (COLS == 128) {
        float4 acc = *reinterpret_cast<const float4*>(&tb[(size_t)warp * 128 + lane * 4]);
        int e = beg;
        for (; e + 8 <= end; e += 8) {
            int s[8];
#pragma unroll
            for (int u = 0; u < 8; u++) s[u] = __ldg(&esrc[e + u]);
            float4 v[8];
#pragma unroll
            for (int u = 0; u < 8; u++)
                v[u] = *reinterpret_cast<const float4*>(&tb[(size_t)s[u] * 128 + lane * 4]);
#pragma unroll
            for (int u = 0; u < 8; u++) {
                acc.x += v[u].x; acc.y += v[u].y; acc.z += v[u].z; acc.w += v[u].w;
            }
        }
        for (; e < end; e++) {
            int s = __ldg(&esrc[e]);
            float4 v = *reinterpret_cast<const float4*>(&tb[(size_t)s * 128 + lane * 4]);
            acc.x += v.x; acc.y += v.y; acc.z += v.z; acc.w += v.w;
        }
        float d = dis[warp];
        float4 b = *reinterpret_cast<const float4*>(&bias[lane * 4]);
        float4 r;
        r.x = fmaf(acc.x, d, b.x);
        r.y = fmaf(acc.y, d, b.y);
        r.z = fmaf(acc.z, d, b.z);
        r.w = fmaf(acc.w, d, b.w);
        if (RELU) {
            r.x = fmaxf(r.x, 0.f); r.y = fmaxf(r.y, 0.f);
            r.z = fmaxf(r.z, 0.f); r.w = fmaxf(r.w, 0.f);
        }
        *reinterpret_cast<float4*>(&out[(size_t)warp * 128 + lane * 4]) = r;
    } else {
        float2 acc = *reinterpret_cast<const float2*>(&tb[(size_t)warp * 64 + lane * 2]);
        int e = beg;
        for (; e + 8 <= end; e += 8) {
            int s[8];
#pragma unroll
            for (int u = 0; u < 8; u++) s[u] = __ldg(&esrc[e + u]);
            float2 v[8];
#pragma unroll
            for (int u = 0; u < 8; u++)
                v[u] = *reinterpret_cast<const float2*>(&tb[(size_t)s[u] * 64 + lane * 2]);
#pragma unroll
            for (int u = 0; u < 8; u++) { acc.x += v[u].x; acc.y += v[u].y; }
        }
        for (; e < end; e++) {
            int s = __ldg(&esrc[e]);
            float2 v = *reinterpret_cast<const float2*>(&tb[(size_t)s * 64 + lane * 2]);
            acc.x += v.x; acc.y += v.y;
        }
        float d = dis[warp];
        float2 b = *reinterpret_cast<const float2*>(&bias[lane * 2]);
        float2 r;
        r.x = fmaf(acc.x, d, b.x);
        r.y = fmaf(acc.y, d, b.y);
        if (RELU) { r.x = fmaxf(r.x, 0.f); r.y = fmaxf(r.y, 0.f); }
        *reinterpret_cast<float2*>(&out[(size_t)warp * 64 + lane * 2]) = r;
    }
}

// ---------------------------------------------------------------- pool
__global__ void k_pool(const float* __restrict__ h, const int* __restrict__ batch,
                       float* __restrict__ out, int n) {
    int gid = blockIdx.x * blockDim.x + threadIdx.x;
    int node = gid / 16;
    int c = (gid % 16) * 4;
    if (node >= n) return;
    int g = batch[node];
    float4 v = *reinterpret_cast<const float4*>(&h[(size_t)node * 64 + c]);
    float* a = &out[(size_t)g * 64 + c];
    asm volatile("red.global.add.v4.f32 [%0], {%1,%2,%3,%4};"
                 :: "l"(a), "f"(v.x), "f"(v.y), "f"(v.z), "f"(v.w) : "memory");
}

// ---------------------------------------------------------------- launch
extern "C" void kernel_launch(void* const* d_in, const int* in_sizes, int n_in,
                              void* d_out, int out_size) {
    const float* x     = (const float*)d_in[0];
    const int*   ei    = (const int*)  d_in[1];
    const int*   batch = (const int*)  d_in[2];
    const float* W_emb = (const float*)d_in[3];
    const float* b_emb = (const float*)d_in[4];
    const float* W1    = (const float*)d_in[5];
    const float* b1    = (const float*)d_in[6];
    const float* W2    = (const float*)d_in[7];
    const float* b2    = (const float*)d_in[8];
    const float* W3    = (const float*)d_in[9];
    const float* b3    = (const float*)d_in[10];

    const int n = in_sizes[2];
    const int e = in_sizes[1] / 2;
    const int* src = ei;
    const int* dst = ei + e;

    float *dis, *h, *t;
    int *rowptr, *esrc;
    cudaGetSymbolAddress((void**)&dis,    g_dis);
    cudaGetSymbolAddress((void**)&rowptr, g_rowptr);
    cudaGetSymbolAddress((void**)&esrc,   g_esrc);
    cudaGetSymbolAddress((void**)&h,      g_h);
    cudaGetSymbolAddress((void**)&t,      g_t);

    auto cdiv = [](long long a, long long b) { return (int)((a + b - 1) / b); };

    // 0: fused prep (CSR + dis)
    k_prep<<<PREP_BLOCKS, PREP_THREADS>>>(src, dst, e, n);
    // 1: zero d_out
    k_zero4<<<cdiv(out_size / 4, 256), 256>>>((float*)d_out, out_size / 4);
    // 2: embedding  h = x @ W_emb + b_emb
    k_gemm<128, false, true><<<cdiv(n, 128), 256>>>(x, W_emb, b_emb, dis, h, n);
    // 3: layer-1 GEMM  t = (h @ W1) * dis   (<- profiled slot)
    k_gemm<128, true, false><<<cdiv(n, 128), 256>>>(h, W1, nullptr, dis, t, n);
    // 4: layer-1 agg
    k_agg<128, true><<<cdiv(n, 8), 256>>>(t, rowptr, esrc, dis, b1, h, n);
    // 5-6: layer 2
    k_gemm<128, true, false><<<cdiv(n, 128), 256>>>(h, W2, nullptr, dis, t, n);
    k_agg<128, true><<<cdiv(n, 8), 256>>>(t, rowptr, esrc, dis, b2, h, n);
    // 7-8: layer 3 (D_OUT = 64, no relu)
    k_gemm<64, true, false><<<cdiv(n, 128), 128>>>(h, W3, nullptr, dis, t, n);
    k_agg<64, false><<<cdiv(n, 8), 256>>>(t, rowptr, esrc, dis, b3, h, n);
    // 9: pool
    k_pool<<<cdiv((long long)n * 16, 256), 256>>>(h, batch, (float*)d_out, n);
}

// round 7
// speedup vs baseline: 1.3792x; 1.3792x over previous
#include <cuda_runtime.h>
#include <cuda_bf16.h>
#include <cstdint>

#define NMAX  100000
#define EMAX  1600000
#define PREP_BLOCKS 128
#define PREP_THREADS 1024

// ---------------------------------------------------------------- scratch
__device__ float    g_dis[NMAX];
__device__ int      g_deg [NMAX];
__device__ int      g_rowptr[NMAX + 1];
__device__ int      g_cursor[NMAX];
__device__ int      g_esrc[EMAX];
__device__ float    g_t [NMAX * 128];      // GEMM fp32 output (agg input)
__device__ float    g_hf[NMAX * 64];       // final fp32 features for pool
__device__ uint32_t g_ahi[NMAX * 64], g_alo[NMAX * 64];  // bf16x2 activations (A set)
__device__ uint32_t g_bhi[NMAX * 64], g_blo[NMAX * 64];  // bf16x2 activations (B set)
__device__ uint32_t g_whi[4][8192], g_wlo[4][8192];      // pre-split W^T images
__device__ int      g_bsum[PREP_BLOCKS];
__device__ int      g_boff[PREP_BLOCKS];
__device__ int      g_total;
__device__ unsigned g_bar;

// ---------------------------------------------------------------- helpers
__device__ __forceinline__ uint32_t sm32(const void* p) {
    uint32_t a;
    asm("{ .reg .u64 t; cvta.to.shared.u64 t, %1; cvt.u32.u64 %0, t; }" : "=r"(a) : "l"(p));
    return a;
}
__device__ __forceinline__ void cpa16(uint32_t dst, const void* src) {
    asm volatile("cp.async.cg.shared.global [%0], [%1], 16;" :: "r"(dst), "l"(src));
}
// split (v0,v1) fp32 -> bf16x2 hi (returned) and bf16x2 lo (out-param)
__device__ __forceinline__ uint32_t packhl(float v0, float v1, uint32_t& lo) {
    __nv_bfloat162 h = __floats2bfloat162_rn(v0, v1);
    uint32_t hb = *reinterpret_cast<uint32_t*>(&h);
    float h0 = __uint_as_float(hb << 16);
    float h1 = __uint_as_float(hb & 0xffff0000u);
    __nv_bfloat162 l = __floats2bfloat162_rn(v0 - h0, v1 - h1);
    lo = *reinterpret_cast<uint32_t*>(&l);
    return hb;
}
// k-pair permuted uint index within a 64-uint (128 bf16) row, m = k-pair index 0..63
__device__ __forceinline__ int widx(int m) {
    int mg = m & 7;
    return ((m >> 3) << 3) + ((mg & 3) << 1) + (mg >> 2);
}
#define MMA_BF16(d, a, b) \
    asm volatile("mma.sync.aligned.m16n8k16.row.col.f32.bf16.bf16.f32 " \
        "{%0,%1,%2,%3}, {%4,%5,%6,%7}, {%8,%9}, {%0,%1,%2,%3};" \
        : "+f"((d)[0]), "+f"((d)[1]), "+f"((d)[2]), "+f"((d)[3]) \
        : "r"((a)[0]), "r"((a)[1]), "r"((a)[2]), "r"((a)[3]), "r"((b).x), "r"((b).y))

// ---------------------------------------------------------------- grid sync
__device__ __forceinline__ void grid_sync(int nb) {
    __syncthreads();
    if (threadIdx.x == 0) {
        __threadfence();
        unsigned ticket = atomicAdd(&g_bar, 1u);
        unsigned phase  = ticket / (unsigned)nb + 1u;
        while (atomicAdd(&g_bar, 0u) < phase * (unsigned)nb) { }
    }
    __syncthreads();
}

// ---------------------------------------------------------------- fused prep
__global__ __launch_bounds__(PREP_THREADS, 1)
void k_prep(const int* __restrict__ src, const int* __restrict__ dst, int e, int n,
            float* __restrict__ d_out, int out4) {
    const int tid  = threadIdx.x;
    const int lane = tid & 31, wid = tid >> 5;
    const int T    = PREP_BLOCKS * PREP_THREADS;
    const int gtid = blockIdx.x * PREP_THREADS + tid;
    __shared__ int sh[32];
    __shared__ int s_boff;

    for (int i = gtid; i < n; i += T) g_deg[i] = 0;
    float4* o4 = reinterpret_cast<float4*>(d_out);
    for (int i = gtid; i < out4; i += T) o4[i] = make_float4(0.f, 0.f, 0.f, 0.f);
    grid_sync(PREP_BLOCKS);

    for (int i = gtid; i < e; i += T) atomicAdd(&g_deg[dst[i]], 1);
    grid_sync(PREP_BLOCKS);

    for (int i = gtid; i < n; i += T) g_dis[i] = rsqrtf((float)g_deg[i] + 1.0f);

    const int per = (n + T - 1) / T;
    const int cb  = gtid * per;
    const int ce  = min(cb + per, n);
    int csum = 0;
    for (int i = cb; i < ce; i++) csum += g_deg[i];

    int x = csum;
#pragma unroll
    for (int o = 1; o < 32; o <<= 1) {
        int y = __shfl_up_sync(0xffffffffu, x, o);
        if (lane >= o) x += y;
    }
    if (lane == 31) sh[wid] = x;
    __syncthreads();
    if (wid == 0) {
        int w = sh[lane];
        int xx = w;
#pragma unroll
        for (int o = 1; o < 32; o <<= 1) {
            int y = __shfl_up_sync(0xffffffffu, xx, o);
            if (lane >= o) xx += y;
        }
        sh[lane] = xx - w;
        if (lane == 31) g_bsum[blockIdx.x] = xx;
    }
    __syncthreads();
    const int thr_excl = x - csum + sh[wid];
    grid_sync(PREP_BLOCKS);

    if (blockIdx.x == 0 && wid == 0) {
        int carry = 0;
        for (int base = 0; base < PREP_BLOCKS; base += 32) {
            int v = g_bsum[base + lane];
            int s = v;
#pragma unroll
            for (int o = 1; o < 32; o <<= 1) {
                int y = __shfl_up_sync(0xffffffffu, s, o);
                if (lane >= o) s += y;
            }
            g_boff[base + lane] = s - v + carry;
            carry += __shfl_sync(0xffffffffu, s, 31);
        }
        if (lane == 0) g_total = carry;
    }
    grid_sync(PREP_BLOCKS);

    if (tid == 0) s_boff = g_boff[blockIdx.x];
    __syncthreads();
    int run = s_boff + thr_excl;
    for (int i = cb; i < ce; i++) {
        g_rowptr[i] = run;
        g_cursor[i] = run;
        run += g_deg[i];
    }
    if (gtid == 0) g_rowptr[n] = g_total;
    grid_sync(PREP_BLOCKS);

    for (int i = gtid; i < e; i += T) {
        int pos = atomicAdd(&g_cursor[dst[i]], 1);
        g_esrc[pos] = src[i];
    }
}

// ---------------------------------------------------------------- weight prep
// Wt images: Wt[n][k] = W[k][n], bf16 hi/lo, k-pair permuted, row = 64 uints.
__global__ void k_wprep(const float* __restrict__ W0, const float* __restrict__ W1,
                        const float* __restrict__ W2, const float* __restrict__ W3) {
    int gid = blockIdx.x * blockDim.x + threadIdx.x;   // 4 * 8192
    int L   = gid >> 13;
    int idx = gid & 8191;
    if (L >= 4) return;
    int N = (L == 3) ? 64 : 128;
    int nn = idx >> 6, m = idx & 63;
    if (nn >= N) return;
    const float* W = (L == 0) ? W0 : (L == 1) ? W1 : (L == 2) ? W2 : W3;
    float v0 = W[(size_t)(2 * m) * N + nn];
    float v1 = W[(size_t)(2 * m + 1) * N + nn];
    uint32_t lo, hi = packhl(v0, v1, lo);
    int w = widx(m);
    g_whi[L][nn * 64 + w] = hi;
    g_wlo[L][nn * 64 + w] = lo;
}

// ---------------------------------------------------------------- x convert
__global__ void k_xconv(const float* __restrict__ x, uint32_t* __restrict__ ohi,
                        uint32_t* __restrict__ olo, int n) {
    int gid = blockIdx.x * blockDim.x + threadIdx.x;   // n * 64
    int node = gid >> 6, m = gid & 63;
    if (node >= n) return;
    float2 v = *reinterpret_cast<const float2*>(&x[(size_t)node * 128 + m * 2]);
    uint32_t lo, hi = packhl(v.x, v.y, lo);
    int w = widx(m);
    ohi[(size_t)node * 64 + w] = hi;
    olo[(size_t)node * 64 + w] = lo;
}

// ---------------------------------------------------------------- mma GEMM
// out[M,BN] = A[M,128] @ W[128,BN]; A given as bf16 hi/lo (k-permuted rows of 64
// uints), W as pre-split Wt images. 3-term split: AhBh + AlBh + AhBl.
// 256 threads, 8 warps (4m x 2n), warp tile 32 x (BN/2), BK=16, cp.async dbuf.
template <int BN, bool SCALE, bool BIAS, bool OBF16>
__global__ void __launch_bounds__(256, 2)
k_mgemm(const uint32_t* __restrict__ Ahi, const uint32_t* __restrict__ Alo,
        const uint32_t* __restrict__ Whi, const uint32_t* __restrict__ Wlo,
        const float* __restrict__ bias, const float* __restrict__ dis,
        float* __restrict__ outf, uint32_t* __restrict__ ohi, uint32_t* __restrict__ olo,
        int M)
{
    constexpr int NT = BN / 16;                 // n-tiles (of 8) per warp
    __shared__ __align__(16) uint32_t sA[2][2][128 * 8];
    __shared__ __align__(16) uint32_t sW[2][2][BN * 8];

    const int tid  = threadIdx.x;
    const int wid  = tid >> 5, lane = tid & 31;
    const int g    = lane >> 2, t = lane & 3;
    const int wm   = wid & 3, wn = wid >> 2;
    const int row0 = blockIdx.x * 128;

    const uint32_t sAb = sm32(sA);
    const uint32_t sWb = sm32(sW);
    constexpr uint32_t A_P = 128 * 8 * 4;       // bytes per (buf, plane)
    constexpr uint32_t W_P = BN * 8 * 4;

    float acc[2][NT][4];
#pragma unroll
    for (int i = 0; i < 2; i++)
#pragma unroll
        for (int j = 0; j < NT; j++)
#pragma unroll
            for (int q = 0; q < 4; q++) acc[i][j][q] = 0.f;

    // tile copy: 16B chunks. A: 256 chunks/plane; W: BN*2 chunks/plane.
    auto issue = [&](int kt, int buf) {
        int r = tid >> 1, h = tid & 1;
        int gr = row0 + r; if (gr >= M) gr = M - 1;
        uint32_t off = (uint32_t)(r * 8 + h * 4) * 4u;
        uint32_t abase = sAb + (uint32_t)buf * 2u * A_P;
        cpa16(abase + off,       Ahi + (size_t)gr * 64 + kt * 8 + h * 4);
        cpa16(abase + A_P + off, Alo + (size_t)gr * 64 + kt * 8 + h * 4);
        if (tid < BN * 2) {
            uint32_t wbase = sWb + (uint32_t)buf * 2u * W_P;
            uint32_t offw = (uint32_t)(r * 8 + h * 4) * 4u;
            cpa16(wbase + offw,       Whi + r * 64 + kt * 8 + h * 4);
            cpa16(wbase + W_P + offw, Wlo + r * 64 + kt * 8 + h * 4);
        }
        asm volatile("cp.async.commit_group;" ::: "memory");
    };

    issue(0, 0);
    for (int kt = 0; kt < 8; kt++) {
        const int buf = kt & 1;
        if (kt < 7) {
            issue(kt + 1, buf ^ 1);
            asm volatile("cp.async.wait_group 1;" ::: "memory");
        } else {
            asm volatile("cp.async.wait_group 0;" ::: "memory");
        }
        __syncthreads();

        const uint32_t* pAh = sA[buf][0];
        const uint32_t* pAl = sA[buf][1];
        const uint32_t* pWh = sW[buf][0];
        const uint32_t* pWl = sW[buf][1];

        uint32_t ah[2][4], al[2][4];
#pragma unroll
        for (int mt = 0; mt < 2; mt++) {
            int r0 = wm * 32 + mt * 16 + g;
            uint2 v;
            v = *reinterpret_cast<const uint2*>(&pAh[r0 * 8 + t * 2]);
            ah[mt][0] = v.x; ah[mt][2] = v.y;
            v = *reinterpret_cast<const uint2*>(&pAh[(r0 + 8) * 8 + t * 2]);
            ah[mt][1] = v.x; ah[mt][3] = v.y;
            v = *reinterpret_cast<const uint2*>(&pAl[r0 * 8 + t * 2]);
            al[mt][0] = v.x; al[mt][2] = v.y;
            v = *reinterpret_cast<const uint2*>(&pAl[(r0 + 8) * 8 + t * 2]);
            al[mt][1] = v.x; al[mt][3] = v.y;
        }
#pragma unroll
        for (int nt = 0; nt < NT; nt++) {
            int rn = wn * (NT * 8) + nt * 8 + g;
            uint2 bh = *reinterpret_cast<const uint2*>(&pWh[rn * 8 + t * 2]);
            uint2 bl = *reinterpret_cast<const uint2*>(&pWl[rn * 8 + t * 2]);
#pragma unroll
            for (int mt = 0; mt < 2; mt++) {
                MMA_BF16(acc[mt][nt], ah[mt], bh);
                MMA_BF16(acc[mt][nt], al[mt], bh);
                MMA_BF16(acc[mt][nt], ah[mt], bl);
            }
        }
        __syncthreads();
    }

    // ---- epilogue ----
#pragma unroll
    for (int mt = 0; mt < 2; mt++) {
        int r0 = row0 + wm * 32 + mt * 16 + g;
        int r1 = r0 + 8;
        bool ok0 = r0 < M, ok1 = r1 < M;
        float sc0 = (SCALE && ok0) ? dis[r0] : 1.0f;
        float sc1 = (SCALE && ok1) ? dis[r1] : 1.0f;
#pragma unroll
        for (int nt = 0; nt < NT; nt++) {
            int c = wn * (NT * 8) + nt * 8 + 2 * t;
            float b0 = 0.f, b1 = 0.f;
            if (BIAS) {
                float2 bb = *reinterpret_cast<const float2*>(&bias[c]);
                b0 = bb.x; b1 = bb.y;
            }
            float v00 = acc[mt][nt][0] * sc0 + b0;
            float v01 = acc[mt][nt][1] * sc0 + b1;
            float v10 = acc[mt][nt][2] * sc1 + b0;
            float v11 = acc[mt][nt][3] * sc1 + b1;
            if (OBF16) {
                int w = widx(c >> 1);
                if (ok0) {
                    uint32_t lo, hi = packhl(v00, v01, lo);
                    ohi[(size_t)r0 * 64 + w] = hi;
                    olo[(size_t)r0 * 64 + w] = lo;
                }
                if (ok1) {
                    uint32_t lo, hi = packhl(v10, v11, lo);
                    ohi[(size_t)r1 * 64 + w] = hi;
                    olo[(size_t)r1 * 64 + w] = lo;
                }
            } else {
                if (ok0) *reinterpret_cast<float2*>(&outf[(size_t)r0 * BN + c]) = make_float2(v00, v01);
                if (ok1) *reinterpret_cast<float2*>(&outf[(size_t)r1 * BN + c]) = make_float2(v10, v11);
            }
        }
    }
}

// ---------------------------------------------------------------- aggregation
// One warp per dst node: res = [relu](dis[d]*(sum tb[nbr] + tb[d]) + bias).
// OBF16: emit hi/lo bf16 (k-permuted) for the next GEMM; else fp32.
template <int COLS, bool RELU, bool OBF16>
__global__ void k_agg(const float* __restrict__ tb, const int* __restrict__ rowptr,
                      const int* __restrict__ esrc, const float* __restrict__ dis,
                      const float* __restrict__ bias, float* __restrict__ outf,
                      uint32_t* __restrict__ ohi, uint32_t* __restrict__ olo, int n) {
    const int warp = (blockIdx.x * blockDim.x + threadIdx.x) >> 5;
    const int lane = threadIdx.x & 31;
    if (warp >= n) return;
    const int beg = __ldg(&rowptr[warp]);
    const int end = __ldg(&rowptr[warp + 1]);

    if constexpr (COLS == 128) {
        float4 acc = *reinterpret_cast<const float4*>(&tb[(size_t)warp * 128 + lane * 4]);
        int e = beg;
        for (; e + 8 <= end; e += 8) {
            int s[8];
#pragma unroll
            for (int u = 0; u < 8; u++) s[u] = __ldg(&esrc[e + u]);
            float4 v[8];
#pragma unroll
            for (int u = 0; u < 8; u++)
                v[u] = *reinterpret_cast<const float4*>(&tb[(size_t)s[u] * 128 + lane * 4]);
#pragma unroll
            for (int u = 0; u < 8; u++) {
                acc.x += v[u].x; acc.y += v[u].y; acc.z += v[u].z; acc.w += v[u].w;
            }
        }
        for (; e < end; e++) {
            int s = __ldg(&esrc[e]);
            float4 v = *reinterpret_cast<const float4*>(&tb[(size_t)s * 128 + lane * 4]);
            acc.x += v.x; acc.y += v.y; acc.z += v.z; acc.w += v.w;
        }
        float d = dis[warp];
        float4 b = *reinterpret_cast<const float4*>(&bias[lane * 4]);
        float4 r;
        r.x = fmaf(acc.x, d, b.x);
        r.y = fmaf(acc.y, d, b.y);
        r.z = fmaf(acc.z, d, b.z);
        r.w = fmaf(acc.w, d, b.w);
        if (RELU) {
            r.x = fmaxf(r.x, 0.f); r.y = fmaxf(r.y, 0.f);
            r.z = fmaxf(r.z, 0.f); r.w = fmaxf(r.w, 0.f);
        }
        if (OBF16) {
            int m0 = lane * 2;
            int w0 = widx(m0), w1 = widx(m0 + 1);
            uint32_t lo0, hi0 = packhl(r.x, r.y, lo0);
            uint32_t lo1, hi1 = packhl(r.z, r.w, lo1);
            ohi[(size_t)warp * 64 + w0] = hi0;
            olo[(size_t)warp * 64 + w0] = lo0;
            ohi[(size_t)warp * 64 + w1] = hi1;
            olo[(size_t)warp * 64 + w1] = lo1;
        } else {
            *reinterpret_cast<float4*>(&outf[(size_t)warp * 128 + lane * 4]) = r;
        }
    } else {  // COLS == 64, fp32 out only (pool input)
        float2 acc = *reinterpret_cast<const float2*>(&tb[(size_t)warp * 64 + lane * 2]);
        int e = beg;
        for (; e + 8 <= end; e += 8) {
            int s[8];
#pragma unroll
            for (int u = 0; u < 8; u++) s[u] = __ldg(&esrc[e + u]);
            float2 v[8];
#pragma unroll
            for (int u = 0; u < 8; u++)
                v[u] = *reinterpret_cast<const float2*>(&tb[(size_t)s[u] * 64 + lane * 2]);
#pragma unroll
            for (int u = 0; u < 8; u++) { acc.x += v[u].x; acc.y += v[u].y; }
        }
        for (; e < end; e++) {
            int s = __ldg(&esrc[e]);
            float2 v = *reinterpret_cast<const float2*>(&tb[(size_t)s * 64 + lane * 2]);
            acc.x += v.x; acc.y += v.y;
        }
        float d = dis[warp];
        float2 b = *reinterpret_cast<const float2*>(&bias[lane * 2]);
        float2 r;
        r.x = fmaf(acc.x, d, b.x);
        r.y = fmaf(acc.y, d, b.y);
        *reinterpret_cast<float2*>(&outf[(size_t)warp * 64 + lane * 2]) = r;
    }
}

// ---------------------------------------------------------------- pool
__global__ void k_pool(const float* __restrict__ h, const int* __restrict__ batch,
                       float* __restrict__ out, int n) {
    int gid = blockIdx.x * blockDim.x + threadIdx.x;
    int node = gid / 16;
    int c = (gid % 16) * 4;
    if (node >= n) return;
    int g = batch[node];
    float4 v = *reinterpret_cast<const float4*>(&h[(size_t)node * 64 + c]);
    float* a = &out[(size_t)g * 64 + c];
    asm volatile("red.global.add.v4.f32 [%0], {%1,%2,%3,%4};"
                 :: "l"(a), "f"(v.x), "f"(v.y), "f"(v.z), "f"(v.w) : "memory");
}

// ---------------------------------------------------------------- launch
extern "C" void kernel_launch(void* const* d_in, const int* in_sizes, int n_in,
                              void* d_out, int out_size) {
    const float* x     = (const float*)d_in[0];
    const int*   ei    = (const int*)  d_in[1];
    const int*   batch = (const int*)  d_in[2];
    const float* W_emb = (const float*)d_in[3];
    const float* b_emb = (const float*)d_in[4];
    const float* W1    = (const float*)d_in[5];
    const float* b1    = (const float*)d_in[6];
    const float* W2    = (const float*)d_in[7];
    const float* b2    = (const float*)d_in[8];
    const float* W3    = (const float*)d_in[9];
    const float* b3    = (const float*)d_in[10];

    const int n = in_sizes[2];
    const int e = in_sizes[1] / 2;
    const int* src = ei;
    const int* dst = ei + e;

    float *dis, *t, *hf;
    int *rowptr, *esrc;
    uint32_t *ahi, *alo, *bhi, *blo, *whi, *wlo;
    cudaGetSymbolAddress((void**)&dis,    g_dis);
    cudaGetSymbolAddress((void**)&rowptr, g_rowptr);
    cudaGetSymbolAddress((void**)&esrc,   g_esrc);
    cudaGetSymbolAddress((void**)&t,      g_t);
    cudaGetSymbolAddress((void**)&hf,     g_hf);
    cudaGetSymbolAddress((void**)&ahi,    g_ahi);
    cudaGetSymbolAddress((void**)&alo,    g_alo);
    cudaGetSymbolAddress((void**)&bhi,    g_bhi);
    cudaGetSymbolAddress((void**)&blo,    g_blo);
    cudaGetSymbolAddress((void**)&whi,    g_whi);
    cudaGetSymbolAddress((void**)&wlo,    g_wlo);

    auto cdiv = [](long long a, long long b) { return (int)((a + b - 1) / b); };

    // 0: fused prep (CSR + dis + zero d_out)
    k_prep<<<PREP_BLOCKS, PREP_THREADS>>>(src, dst, e, n, (float*)d_out, out_size / 4);
    // 1: weight split + transpose + permute
    k_wprep<<<cdiv(4 * 8192, 256), 256>>>(W_emb, W1, W2, W3);
    // 2: x -> bf16 hi/lo
    k_xconv<<<cdiv((long long)n * 64, 256), 256>>>(x, ahi, alo, n);
    // 3: embedding  (A set) -> h bf16 (B set)   (<- profiled slot)
    k_mgemm<128, false, true, true><<<cdiv(n, 128), 256>>>(
        ahi, alo, whi + 0 * 8192, wlo + 0 * 8192, b_emb, dis, nullptr, bhi, blo, n);
    // 4: layer-1 GEMM  t = (h @ W1) * dis
    k_mgemm<128, true, false, false><<<cdiv(n, 128), 256>>>(
        bhi, blo, whi + 1 * 8192, wlo + 1 * 8192, nullptr, dis, t, nullptr, nullptr, n);
    // 5: layer-1 agg -> bf16 (A set)
    k_agg<128, true, true><<<cdiv(n, 8), 256>>>(t, rowptr, esrc, dis, b1, nullptr, ahi, alo, n);
    // 6-7: layer 2
    k_mgemm<128, true, false, false><<<cdiv(n, 128), 256>>>(
        ahi, alo, whi + 2 * 8192, wlo + 2 * 8192, nullptr, dis, t, nullptr, nullptr, n);
    k_agg<128, true, true><<<cdiv(n, 8), 256>>>(t, rowptr, esrc, dis, b2, nullptr, bhi, blo, n);
    // 8-9: layer 3 (BN = 64, no relu, fp32 out)
    k_mgemm<64, true, false, false><<<cdiv(n, 128), 256>>>(
        bhi, blo, whi + 3 * 8192, wlo + 3 * 8192, nullptr, dis, t, nullptr, nullptr, n);
    k_agg<64, false, false><<<cdiv(n, 8), 256>>>(t, rowptr, esrc, dis, b3, hf, nullptr, nullptr, n);
    // 10: pool
    k_pool<<<cdiv((long long)n * 16, 256), 256>>>(hf, batch, (float*)d_out, n);
}

// round 8
// speedup vs baseline: 1.4824x; 1.0748x over previous
#include <cuda_runtime.h>
#include <cuda_bf16.h>
#include <cuda_fp16.h>
#include <cstdint>

#define NMAX  100000
#define EMAX  1600000
#define PREP_BLOCKS 128
#define PREP_THREADS 1024

// ---------------------------------------------------------------- scratch
__device__ float    g_dis[NMAX];
__device__ int      g_deg [NMAX];
__device__ int      g_rowptr[NMAX + 1];
__device__ int      g_cursor[NMAX];
__device__ int      g_esrc[EMAX];
__device__ uint32_t g_t16[NMAX * 64];      // GEMM output as half2 pairs (agg input)
__device__ uint32_t g_ahi[NMAX * 64], g_alo[NMAX * 64];  // bf16x2 activations (A set)
__device__ uint32_t g_bhi[NMAX * 64], g_blo[NMAX * 64];  // bf16x2 activations (B set)
__device__ uint32_t g_whi[4][8192], g_wlo[4][8192];      // pre-split W^T images
__device__ int      g_bsum[PREP_BLOCKS];
__device__ int      g_boff[PREP_BLOCKS];
__device__ int      g_total;
__device__ unsigned g_bar;

// ---------------------------------------------------------------- helpers
__device__ __forceinline__ uint32_t sm32(const void* p) {
    uint32_t a;
    asm("{ .reg .u64 t; cvta.to.shared.u64 t, %1; cvt.u32.u64 %0, t; }" : "=r"(a) : "l"(p));
    return a;
}
__device__ __forceinline__ void cpa16(uint32_t dst, const void* src) {
    asm volatile("cp.async.cg.shared.global [%0], [%1], 16;" :: "r"(dst), "l"(src));
}
__device__ __forceinline__ uint32_t packhl(float v0, float v1, uint32_t& lo) {
    __nv_bfloat162 h = __floats2bfloat162_rn(v0, v1);
    uint32_t hb = *reinterpret_cast<uint32_t*>(&h);
    float h0 = __uint_as_float(hb << 16);
    float h1 = __uint_as_float(hb & 0xffff0000u);
    __nv_bfloat162 l = __floats2bfloat162_rn(v0 - h0, v1 - h1);
    lo = *reinterpret_cast<uint32_t*>(&l);
    return hb;
}
__device__ __forceinline__ uint32_t packh2(float v0, float v1) {
    __half2 h = __floats2half2_rn(v0, v1);
    return *reinterpret_cast<uint32_t*>(&h);
}
__device__ __forceinline__ float2 unph2(uint32_t u) {
    return __half22float2(*reinterpret_cast<__half2*>(&u));
}
// k-pair permuted uint index within a 64-uint (128 bf16) row, m = k-pair index 0..63
__device__ __forceinline__ int widx(int m) {
    int mg = m & 7;
    return ((m >> 3) << 3) + ((mg & 3) << 1) + (mg >> 2);
}
#define MMA_BF16(d, a, b) \
    asm volatile("mma.sync.aligned.m16n8k16.row.col.f32.bf16.bf16.f32 " \
        "{%0,%1,%2,%3}, {%4,%5,%6,%7}, {%8,%9}, {%0,%1,%2,%3};" \
        : "+f"((d)[0]), "+f"((d)[1]), "+f"((d)[2]), "+f"((d)[3]) \
        : "r"((a)[0]), "r"((a)[1]), "r"((a)[2]), "r"((a)[3]), "r"((b).x), "r"((b).y))

// ---------------------------------------------------------------- grid sync
__device__ __forceinline__ void grid_sync(int nb) {
    __syncthreads();
    if (threadIdx.x == 0) {
        __threadfence();
        unsigned ticket = atomicAdd(&g_bar, 1u);
        unsigned phase  = ticket / (unsigned)nb + 1u;
        while (atomicAdd(&g_bar, 0u) < phase * (unsigned)nb) { }
    }
    __syncthreads();
}

// ---------------------------------------------------------------- fused prep
__global__ __launch_bounds__(PREP_THREADS, 1)
void k_prep(const int* __restrict__ src, const int* __restrict__ dst, int e, int n,
            float* __restrict__ d_out, int out4) {
    const int tid  = threadIdx.x;
    const int lane = tid & 31, wid = tid >> 5;
    const int T    = PREP_BLOCKS * PREP_THREADS;
    const int gtid = blockIdx.x * PREP_THREADS + tid;
    __shared__ int sh[32];
    __shared__ int s_boff;

    for (int i = gtid; i < n; i += T) g_deg[i] = 0;
    float4* o4 = reinterpret_cast<float4*>(d_out);
    for (int i = gtid; i < out4; i += T) o4[i] = make_float4(0.f, 0.f, 0.f, 0.f);
    grid_sync(PREP_BLOCKS);

    for (int i = gtid; i < e; i += T) atomicAdd(&g_deg[dst[i]], 1);
    grid_sync(PREP_BLOCKS);

    for (int i = gtid; i < n; i += T) g_dis[i] = rsqrtf((float)g_deg[i] + 1.0f);

    const int per = (n + T - 1) / T;
    const int cb  = gtid * per;
    const int ce  = min(cb + per, n);
    int csum = 0;
    for (int i = cb; i < ce; i++) csum += g_deg[i];

    int x = csum;
#pragma unroll
    for (int o = 1; o < 32; o <<= 1) {
        int y = __shfl_up_sync(0xffffffffu, x, o);
        if (lane >= o) x += y;
    }
    if (lane == 31) sh[wid] = x;
    __syncthreads();
    if (wid == 0) {
        int w = sh[lane];
        int xx = w;
#pragma unroll
        for (int o = 1; o < 32; o <<= 1) {
            int y = __shfl_up_sync(0xffffffffu, xx, o);
            if (lane >= o) xx += y;
        }
        sh[lane] = xx - w;
        if (lane == 31) g_bsum[blockIdx.x] = xx;
    }
    __syncthreads();
    const int thr_excl = x - csum + sh[wid];
    grid_sync(PREP_BLOCKS);

    if (blockIdx.x == 0 && wid == 0) {
        int carry = 0;
        for (int base = 0; base < PREP_BLOCKS; base += 32) {
            int v = g_bsum[base + lane];
            int s = v;
#pragma unroll
            for (int o = 1; o < 32; o <<= 1) {
                int y = __shfl_up_sync(0xffffffffu, s, o);
                if (lane >= o) s += y;
            }
            g_boff[base + lane] = s - v + carry;
            carry += __shfl_sync(0xffffffffu, s, 31);
        }
        if (lane == 0) g_total = carry;
    }
    grid_sync(PREP_BLOCKS);

    if (tid == 0) s_boff = g_boff[blockIdx.x];
    __syncthreads();
    int run = s_boff + thr_excl;
    for (int i = cb; i < ce; i++) {
        g_rowptr[i] = run;
        g_cursor[i] = run;
        run += g_deg[i];
    }
    if (gtid == 0) g_rowptr[n] = g_total;
    grid_sync(PREP_BLOCKS);

    for (int i = gtid; i < e; i += T) {
        int pos = atomicAdd(&g_cursor[dst[i]], 1);
        g_esrc[pos] = src[i];
    }
}

// ---------------------------------------------------------------- weight prep
__global__ void k_wprep(const float* __restrict__ W0, const float* __restrict__ W1,
                        const float* __restrict__ W2, const float* __restrict__ W3) {
    int gid = blockIdx.x * blockDim.x + threadIdx.x;   // 4 * 8192
    int L   = gid >> 13;
    int idx = gid & 8191;
    if (L >= 4) return;
    int N = (L == 3) ? 64 : 128;
    int nn = idx >> 6, m = idx & 63;
    if (nn >= N) return;
    const float* W = (L == 0) ? W0 : (L == 1) ? W1 : (L == 2) ? W2 : W3;
    float v0 = W[(size_t)(2 * m) * N + nn];
    float v1 = W[(size_t)(2 * m + 1) * N + nn];
    uint32_t lo, hi = packhl(v0, v1, lo);
    int w = widx(m);
    g_whi[L][nn * 64 + w] = hi;
    g_wlo[L][nn * 64 + w] = lo;
}

// ---------------------------------------------------------------- x convert
__global__ void k_xconv(const float* __restrict__ x, uint32_t* __restrict__ ohi,
                        uint32_t* __restrict__ olo, int n) {
    int gid = blockIdx.x * blockDim.x + threadIdx.x;   // n * 64
    int node = gid >> 6, m = gid & 63;
    if (node >= n) return;
    float2 v = *reinterpret_cast<const float2*>(&x[(size_t)node * 128 + m * 2]);
    uint32_t lo, hi = packhl(v.x, v.y, lo);
    int w = widx(m);
    ohi[(size_t)node * 64 + w] = hi;
    olo[(size_t)node * 64 + w] = lo;
}

// ---------------------------------------------------------------- mma GEMM
// out[M,BN] = A[M,128] @ W[128,BN]; 3-term bf16 split: AhBh + AlBh + AhBl.
// OBF16: emit bf16 hi/lo (k-permuted) for next GEMM; else fp16 half2 into out16.
template <int BN, bool SCALE, bool BIAS, bool OBF16>
__global__ void __launch_bounds__(256, 2)
k_mgemm(const uint32_t* __restrict__ Ahi, const uint32_t* __restrict__ Alo,
        const uint32_t* __restrict__ Whi, const uint32_t* __restrict__ Wlo,
        const float* __restrict__ bias, const float* __restrict__ dis,
        uint32_t* __restrict__ out16, uint32_t* __restrict__ ohi,
        uint32_t* __restrict__ olo, int M)
{
    constexpr int NT = BN / 16;
    __shared__ __align__(16) uint32_t sA[2][2][128 * 8];
    __shared__ __align__(16) uint32_t sW[2][2][BN * 8];

    const int tid  = threadIdx.x;
    const int wid  = tid >> 5, lane = tid & 31;
    const int g    = lane >> 2, t = lane & 3;
    const int wm   = wid & 3, wn = wid >> 2;
    const int row0 = blockIdx.x * 128;

    const uint32_t sAb = sm32(sA);
    const uint32_t sWb = sm32(sW);
    constexpr uint32_t A_P = 128 * 8 * 4;
    constexpr uint32_t W_P = BN * 8 * 4;

    float acc[2][NT][4];
#pragma unroll
    for (int i = 0; i < 2; i++)
#pragma unroll
        for (int j = 0; j < NT; j++)
#pragma unroll
            for (int q = 0; q < 4; q++) acc[i][j][q] = 0.f;

    auto issue = [&](int kt, int buf) {
        int r = tid >> 1, h = tid & 1;
        int gr = row0 + r; if (gr >= M) gr = M - 1;
        uint32_t off = (uint32_t)(r * 8 + h * 4) * 4u;
        uint32_t abase = sAb + (uint32_t)buf * 2u * A_P;
        cpa16(abase + off,       Ahi + (size_t)gr * 64 + kt * 8 + h * 4);
        cpa16(abase + A_P + off, Alo + (size_t)gr * 64 + kt * 8 + h * 4);
        if (tid < BN * 2) {
            uint32_t wbase = sWb + (uint32_t)buf * 2u * W_P;
            uint32_t offw = (uint32_t)(r * 8 + h * 4) * 4u;
            cpa16(wbase + offw,       Whi + r * 64 + kt * 8 + h * 4);
            cpa16(wbase + W_P + offw, Wlo + r * 64 + kt * 8 + h * 4);
        }
        asm volatile("cp.async.commit_group;" ::: "memory");
    };

    issue(0, 0);
    for (int kt = 0; kt < 8; kt++) {
        const int buf = kt & 1;
        if (kt < 7) {
            issue(kt + 1, buf ^ 1);
            asm volatile("cp.async.wait_group 1;" ::: "memory");
        } else {
            asm volatile("cp.async.wait_group 0;" ::: "memory");
        }
        __syncthreads();

        const uint32_t* pAh = sA[buf][0];
        const uint32_t* pAl = sA[buf][1];
        const uint32_t* pWh = sW[buf][0];
        const uint32_t* pWl = sW[buf][1];

        uint32_t ah[2][4], al[2][4];
#pragma unroll
        for (int mt = 0; mt < 2; mt++) {
            int r0 = wm * 32 + mt * 16 + g;
            uint2 v;
            v = *reinterpret_cast<const uint2*>(&pAh[r0 * 8 + t * 2]);
            ah[mt][0] = v.x; ah[mt][2] = v.y;
            v = *reinterpret_cast<const uint2*>(&pAh[(r0 + 8) * 8 + t * 2]);
            ah[mt][1] = v.x; ah[mt][3] = v.y;
            v = *reinterpret_cast<const uint2*>(&pAl[r0 * 8 + t * 2]);
            al[mt][0] = v.x; al[mt][2] = v.y;
            v = *reinterpret_cast<const uint2*>(&pAl[(r0 + 8) * 8 + t * 2]);
            al[mt][1] = v.x; al[mt][3] = v.y;
        }
#pragma unroll
        for (int nt = 0; nt < NT; nt++) {
            int rn = wn * (NT * 8) + nt * 8 + g;
            uint2 bh = *reinterpret_cast<const uint2*>(&pWh[rn * 8 + t * 2]);
            uint2 bl = *reinterpret_cast<const uint2*>(&pWl[rn * 8 + t * 2]);
#pragma unroll
            for (int mt = 0; mt < 2; mt++) {
                MMA_BF16(acc[mt][nt], ah[mt], bh);
                MMA_BF16(acc[mt][nt], al[mt], bh);
                MMA_BF16(acc[mt][nt], ah[mt], bl);
            }
        }
        __syncthreads();
    }

    // ---- epilogue ----
#pragma unroll
    for (int mt = 0; mt < 2; mt++) {
        int r0 = row0 + wm * 32 + mt * 16 + g;
        int r1 = r0 + 8;
        bool ok0 = r0 < M, ok1 = r1 < M;
        float sc0 = (SCALE && ok0) ? dis[r0] : 1.0f;
        float sc1 = (SCALE && ok1) ? dis[r1] : 1.0f;
#pragma unroll
        for (int nt = 0; nt < NT; nt++) {
            int c = wn * (NT * 8) + nt * 8 + 2 * t;
            float b0 = 0.f, b1 = 0.f;
            if (BIAS) {
                float2 bb = *reinterpret_cast<const float2*>(&bias[c]);
                b0 = bb.x; b1 = bb.y;
            }
            float v00 = acc[mt][nt][0] * sc0 + b0;
            float v01 = acc[mt][nt][1] * sc0 + b1;
            float v10 = acc[mt][nt][2] * sc1 + b0;
            float v11 = acc[mt][nt][3] * sc1 + b1;
            if (OBF16) {
                int w = widx(c >> 1);
                if (ok0) {
                    uint32_t lo, hi = packhl(v00, v01, lo);
                    ohi[(size_t)r0 * 64 + w] = hi;
                    olo[(size_t)r0 * 64 + w] = lo;
                }
                if (ok1) {
                    uint32_t lo, hi = packhl(v10, v11, lo);
                    ohi[(size_t)r1 * 64 + w] = hi;
                    olo[(size_t)r1 * 64 + w] = lo;
                }
            } else {
                if (ok0) out16[(size_t)r0 * (BN / 2) + (c >> 1)] = packh2(v00, v01);
                if (ok1) out16[(size_t)r1 * (BN / 2) + (c >> 1)] = packh2(v10, v11);
            }
        }
    }
}

// ---------------------------------------------------------------- aggregation
// One warp per dst node; tb16 holds half2-packed GEMM output.
// COLS==128: emit bf16 hi/lo for the next GEMM. COLS==64: fused pool via red.v2.
template <int COLS, bool RELU>
__global__ void k_agg(const uint32_t* __restrict__ tb16, const int* __restrict__ rowptr,
                      const int* __restrict__ esrc, const float* __restrict__ dis,
                      const float* __restrict__ bias, uint32_t* __restrict__ ohi,
                      uint32_t* __restrict__ olo, const int* __restrict__ batch,
                      float* __restrict__ dout, int n) {
    const int warp = (blockIdx.x * blockDim.x + threadIdx.x) >> 5;
    const int lane = threadIdx.x & 31;
    if (warp >= n) return;
    const int beg = __ldg(&rowptr[warp]);
    const int end = __ldg(&rowptr[warp + 1]);

    if constexpr (COLS == 128) {
        uint2 sv = *reinterpret_cast<const uint2*>(&tb16[(size_t)warp * 64 + lane * 2]);
        float2 a0 = unph2(sv.x), a1 = unph2(sv.y);
        float4 acc = make_float4(a0.x, a0.y, a1.x, a1.y);
        int e = beg;
        for (; e + 8 <= end; e += 8) {
            int s[8];
#pragma unroll
            for (int u = 0; u < 8; u++) s[u] = __ldg(&esrc[e + u]);
            uint2 v[8];
#pragma unroll
            for (int u = 0; u < 8; u++)
                v[u] = *reinterpret_cast<const uint2*>(&tb16[(size_t)s[u] * 64 + lane * 2]);
#pragma unroll
            for (int u = 0; u < 8; u++) {
                float2 f0 = unph2(v[u].x), f1 = unph2(v[u].y);
                acc.x += f0.x; acc.y += f0.y; acc.z += f1.x; acc.w += f1.y;
            }
        }
        for (; e < end; e++) {
            int s = __ldg(&esrc[e]);
            uint2 v = *reinterpret_cast<const uint2*>(&tb16[(size_t)s * 64 + lane * 2]);
            float2 f0 = unph2(v.x), f1 = unph2(v.y);
            acc.x += f0.x; acc.y += f0.y; acc.z += f1.x; acc.w += f1.y;
        }
        float d = dis[warp];
        float4 b = *reinterpret_cast<const float4*>(&bias[lane * 4]);
        float4 r;
        r.x = fmaf(acc.x, d, b.x);
        r.y = fmaf(acc.y, d, b.y);
        r.z = fmaf(acc.z, d, b.z);
        r.w = fmaf(acc.w, d, b.w);
        if (RELU) {
            r.x = fmaxf(r.x, 0.f); r.y = fmaxf(r.y, 0.f);
            r.z = fmaxf(r.z, 0.f); r.w = fmaxf(r.w, 0.f);
        }
        int m0 = lane * 2;
        int w0 = widx(m0), w1 = widx(m0 + 1);
        uint32_t lo0, hi0 = packhl(r.x, r.y, lo0);
        uint32_t lo1, hi1 = packhl(r.z, r.w, lo1);
        ohi[(size_t)warp * 64 + w0] = hi0;
        olo[(size_t)warp * 64 + w0] = lo0;
        ohi[(size_t)warp * 64 + w1] = hi1;
        olo[(size_t)warp * 64 + w1] = lo1;
    } else {  // COLS == 64: fused pool
        float2 acc = unph2(tb16[(size_t)warp * 32 + lane]);
        int e = beg;
        for (; e + 8 <= end; e += 8) {
            int s[8];
#pragma unroll
            for (int u = 0; u < 8; u++) s[u] = __ldg(&esrc[e + u]);
            uint32_t v[8];
#pragma unroll
            for (int u = 0; u < 8; u++) v[u] = tb16[(size_t)s[u] * 32 + lane];
#pragma unroll
            for (int u = 0; u < 8; u++) {
                float2 f = unph2(v[u]);
                acc.x += f.x; acc.y += f.y;
            }
        }
        for (; e < end; e++) {
            int s = __ldg(&esrc[e]);
            float2 f = unph2(tb16[(size_t)s * 32 + lane]);
            acc.x += f.x; acc.y += f.y;
        }
        float d = dis[warp];
        float2 b = *reinterpret_cast<const float2*>(&bias[lane * 2]);
        float rx = fmaf(acc.x, d, b.x);
        float ry = fmaf(acc.y, d, b.y);
        int gidx = __ldg(&batch[warp]);
        float* a = &dout[(size_t)gidx * 64 + lane * 2];
        asm volatile("red.global.add.v2.f32 [%0], {%1,%2};"
                     :: "l"(a), "f"(rx), "f"(ry) : "memory");
    }
}

// ---------------------------------------------------------------- launch
extern "C" void kernel_launch(void* const* d_in, const int* in_sizes, int n_in,
                              void* d_out, int out_size) {
    const float* x     = (const float*)d_in[0];
    const int*   ei    = (const int*)  d_in[1];
    const int*   batch = (const int*)  d_in[2];
    const float* W_emb = (const float*)d_in[3];
    const float* b_emb = (const float*)d_in[4];
    const float* W1    = (const float*)d_in[5];
    const float* b1    = (const float*)d_in[6];
    const float* W2    = (const float*)d_in[7];
    const float* b2    = (const float*)d_in[8];
    const float* W3    = (const float*)d_in[9];
    const float* b3    = (const float*)d_in[10];

    const int n = in_sizes[2];
    const int e = in_sizes[1] / 2;
    const int* src = ei;
    const int* dst = ei + e;

    float *dis;
    int *rowptr, *esrc;
    uint32_t *t16, *ahi, *alo, *bhi, *blo, *whi, *wlo;
    cudaGetSymbolAddress((void**)&dis,    g_dis);
    cudaGetSymbolAddress((void**)&rowptr, g_rowptr);
    cudaGetSymbolAddress((void**)&esrc,   g_esrc);
    cudaGetSymbolAddress((void**)&t16,    g_t16);
    cudaGetSymbolAddress((void**)&ahi,    g_ahi);
    cudaGetSymbolAddress((void**)&alo,    g_alo);
    cudaGetSymbolAddress((void**)&bhi,    g_bhi);
    cudaGetSymbolAddress((void**)&blo,    g_blo);
    cudaGetSymbolAddress((void**)&whi,    g_whi);
    cudaGetSymbolAddress((void**)&wlo,    g_wlo);

    auto cdiv = [](long long a, long long b) { return (int)((a + b - 1) / b); };

    // 0: fused prep (CSR + dis + zero d_out)
    k_prep<<<PREP_BLOCKS, PREP_THREADS>>>(src, dst, e, n, (float*)d_out, out_size / 4);
    // 1: weight split + transpose + permute
    k_wprep<<<cdiv(4 * 8192, 256), 256>>>(W_emb, W1, W2, W3);
    // 2: x -> bf16 hi/lo
    k_xconv<<<cdiv((long long)n * 64, 256), 256>>>(x, ahi, alo, n);
    // 3: embedding  (A set) -> h bf16 (B set)   (<- profiled slot)
    k_mgemm<128, false, true, true><<<cdiv(n, 128), 256>>>(
        ahi, alo, whi + 0 * 8192, wlo + 0 * 8192, b_emb, dis, nullptr, bhi, blo, n);
    // 4: layer-1 GEMM  t16 = fp16((h @ W1) * dis)
    k_mgemm<128, true, false, false><<<cdiv(n, 128), 256>>>(
        bhi, blo, whi + 1 * 8192, wlo + 1 * 8192, nullptr, dis, t16, nullptr, nullptr, n);
    // 5: layer-1 agg -> bf16 (A set)
    k_agg<128, true><<<cdiv(n, 8), 256>>>(t16, rowptr, esrc, dis, b1, ahi, alo,
                                          nullptr, nullptr, n);
    // 6-7: layer 2
    k_mgemm<128, true, false, false><<<cdiv(n, 128), 256>>>(
        ahi, alo, whi + 2 * 8192, wlo + 2 * 8192, nullptr, dis, t16, nullptr, nullptr, n);
    k_agg<128, true><<<cdiv(n, 8), 256>>>(t16, rowptr, esrc, dis, b2, bhi, blo,
                                          nullptr, nullptr, n);
    // 8-9: layer 3 (BN = 64, no relu) + fused pool
    k_mgemm<64, true, false, false><<<cdiv(n, 128), 256>>>(
        bhi, blo, whi + 3 * 8192, wlo + 3 * 8192, nullptr, dis, t16, nullptr, nullptr, n);
    k_agg<64, false><<<cdiv(n, 8), 256>>>(t16, rowptr, esrc, dis, b3, nullptr, nullptr,
                                          batch, (float*)d_out, n);
}

// round 9
// speedup vs baseline: 1.6209x; 1.0934x over previous
#include <cuda_runtime.h>
#include <cuda_bf16.h>
#include <cuda_fp16.h>
#include <cstdint>

#define NMAX  100000
#define EMAX  1600000
#define PREP_BLOCKS 128
#define PREP_THREADS 1024

// ---------------------------------------------------------------- scratch
__device__ float    g_dis[NMAX];
__device__ int      g_deg [NMAX];
__device__ int      g_rowptr[NMAX + 1];
__device__ int      g_cursor[NMAX];
__device__ int      g_esrc[EMAX];
__device__ uint32_t g_t16[NMAX * 64];      // GEMM output as half2 pairs (agg input)
__device__ uint32_t g_ahi[NMAX * 64], g_alo[NMAX * 64];  // bf16x2 activations (A set)
__device__ uint32_t g_bhi[NMAX * 64], g_blo[NMAX * 64];  // bf16x2 activations (B set)
__device__ uint32_t g_whi[4][8192], g_wlo[4][8192];      // pre-split W^T images
__device__ float    g_bc[128];             // b_emb @ W1
__device__ int      g_bsum[PREP_BLOCKS];
__device__ int      g_boff[PREP_BLOCKS];
__device__ int      g_total;
__device__ unsigned g_bar;

// ---------------------------------------------------------------- helpers
__device__ __forceinline__ uint32_t sm32(const void* p) {
    uint32_t a;
    asm("{ .reg .u64 t; cvta.to.shared.u64 t, %1; cvt.u32.u64 %0, t; }" : "=r"(a) : "l"(p));
    return a;
}
__device__ __forceinline__ void cpa16(uint32_t dst, const void* src) {
    asm volatile("cp.async.cg.shared.global [%0], [%1], 16;" :: "r"(dst), "l"(src));
}
__device__ __forceinline__ uint32_t packhl(float v0, float v1, uint32_t& lo) {
    __nv_bfloat162 h = __floats2bfloat162_rn(v0, v1);
    uint32_t hb = *reinterpret_cast<uint32_t*>(&h);
    float h0 = __uint_as_float(hb << 16);
    float h1 = __uint_as_float(hb & 0xffff0000u);
    __nv_bfloat162 l = __floats2bfloat162_rn(v0 - h0, v1 - h1);
    lo = *reinterpret_cast<uint32_t*>(&l);
    return hb;
}
__device__ __forceinline__ uint32_t packh2(float v0, float v1) {
    __half2 h = __floats2half2_rn(v0, v1);
    return *reinterpret_cast<uint32_t*>(&h);
}
__device__ __forceinline__ float2 unph2(uint32_t u) {
    return __half22float2(*reinterpret_cast<__half2*>(&u));
}
// k-pair permuted uint index within a 64-uint (128 bf16) row, m = k-pair index 0..63
__device__ __forceinline__ int widx(int m) {
    int mg = m & 7;
    return ((m >> 3) << 3) + ((mg & 3) << 1) + (mg >> 2);
}
#define MMA_BF16(d, a, b) \
    asm volatile("mma.sync.aligned.m16n8k16.row.col.f32.bf16.bf16.f32 " \
        "{%0,%1,%2,%3}, {%4,%5,%6,%7}, {%8,%9}, {%0,%1,%2,%3};" \
        : "+f"((d)[0]), "+f"((d)[1]), "+f"((d)[2]), "+f"((d)[3]) \
        : "r"((a)[0]), "r"((a)[1]), "r"((a)[2]), "r"((a)[3]), "r"((b).x), "r"((b).y))

// ---------------------------------------------------------------- grid sync
__device__ __forceinline__ void grid_sync(int nb) {
    __syncthreads();
    if (threadIdx.x == 0) {
        __threadfence();
        unsigned ticket = atomicAdd(&g_bar, 1u);
        unsigned phase  = ticket / (unsigned)nb + 1u;
        while (atomicAdd(&g_bar, 0u) < phase * (unsigned)nb) { }
    }
    __syncthreads();
}

// ---------------------------------------------------------------- fused prep
__global__ __launch_bounds__(PREP_THREADS, 1)
void k_prep(const int* __restrict__ src, const int* __restrict__ dst, int e, int n,
            float* __restrict__ d_out, int out4) {
    const int tid  = threadIdx.x;
    const int lane = tid & 31, wid = tid >> 5;
    const int T    = PREP_BLOCKS * PREP_THREADS;
    const int gtid = blockIdx.x * PREP_THREADS + tid;
    __shared__ int sh[32];
    __shared__ int s_boff;

    for (int i = gtid; i < n; i += T) g_deg[i] = 0;
    float4* o4 = reinterpret_cast<float4*>(d_out);
    for (int i = gtid; i < out4; i += T) o4[i] = make_float4(0.f, 0.f, 0.f, 0.f);
    grid_sync(PREP_BLOCKS);

    for (int i = gtid; i < e; i += T) atomicAdd(&g_deg[dst[i]], 1);
    grid_sync(PREP_BLOCKS);

    for (int i = gtid; i < n; i += T) g_dis[i] = rsqrtf((float)g_deg[i] + 1.0f);

    const int per = (n + T - 1) / T;
    const int cb  = gtid * per;
    const int ce  = min(cb + per, n);
    int csum = 0;
    for (int i = cb; i < ce; i++) csum += g_deg[i];

    int x = csum;
#pragma unroll
    for (int o = 1; o < 32; o <<= 1) {
        int y = __shfl_up_sync(0xffffffffu, x, o);
        if (lane >= o) x += y;
    }
    if (lane == 31) sh[wid] = x;
    __syncthreads();
    if (wid == 0) {
        int w = sh[lane];
        int xx = w;
#pragma unroll
        for (int o = 1; o < 32; o <<= 1) {
            int y = __shfl_up_sync(0xffffffffu, xx, o);
            if (lane >= o) xx += y;
        }
        sh[lane] = xx - w;
        if (lane == 31) g_bsum[blockIdx.x] = xx;
    }
    __syncthreads();
    const int thr_excl = x - csum + sh[wid];
    grid_sync(PREP_BLOCKS);

    if (blockIdx.x == 0 && wid == 0) {
        int carry = 0;
        for (int base = 0; base < PREP_BLOCKS; base += 32) {
            int v = g_bsum[base + lane];
            int s = v;
#pragma unroll
            for (int o = 1; o < 32; o <<= 1) {
                int y = __shfl_up_sync(0xffffffffu, s, o);
                if (lane >= o) s += y;
            }
            g_boff[base + lane] = s - v + carry;
            carry += __shfl_sync(0xffffffffu, s, 31);
        }
        if (lane == 0) g_total = carry;
    }
    grid_sync(PREP_BLOCKS);

    if (tid == 0) s_boff = g_boff[blockIdx.x];
    __syncthreads();
    int run = s_boff + thr_excl;
    for (int i = cb; i < ce; i++) {
        g_rowptr[i] = run;
        g_cursor[i] = run;
        run += g_deg[i];
    }
    if (gtid == 0) g_rowptr[n] = g_total;
    grid_sync(PREP_BLOCKS);

    for (int i = gtid; i < e; i += T) {
        int pos = atomicAdd(&g_cursor[dst[i]], 1);
        g_esrc[pos] = src[i];
    }
}

// ---------------------------------------------------------------- weight prep
// Images for W2 (slot 2) and W3 (slot 3) only; slot 0 is built by k_wcomb.
__global__ void k_wprep(const float* __restrict__ W2, const float* __restrict__ W3) {
    int gid = blockIdx.x * blockDim.x + threadIdx.x;   // 2 * 8192
    int L   = 2 + (gid >> 13);
    int idx = gid & 8191;
    if (L > 3) return;
    int N = (L == 3) ? 64 : 128;
    int nn = idx >> 6, m = idx & 63;
    if (nn >= N) return;
    const float* W = (L == 2) ? W2 : W3;
    float v0 = W[(size_t)(2 * m) * N + nn];
    float v1 = W[(size_t)(2 * m + 1) * N + nn];
    uint32_t lo, hi = packhl(v0, v1, lo);
    int w = widx(m);
    g_whi[L][nn * 64 + w] = hi;
    g_wlo[L][nn * 64 + w] = lo;
}

// ---------------------------------------------------------------- combined weight
// Wc = W_emb @ W1 (128x128, fp32), split hi/lo into image slot 0.
// Also bc = b_emb @ W1 (block 0, first 128 threads).
__global__ void k_wcomb(const float* __restrict__ We, const float* __restrict__ W1,
                        const float* __restrict__ be) {
    int gid = blockIdx.x * blockDim.x + threadIdx.x;   // 64 * 128 = 8192
    int m = gid >> 7, nn = gid & 127;                  // m = k-pair, nn = out col
    if (m < 64) {
        float v0 = 0.f, v1 = 0.f;
        const float* r0 = &We[(size_t)(2 * m) * 128];
        const float* r1 = &We[(size_t)(2 * m + 1) * 128];
#pragma unroll 4
        for (int j = 0; j < 128; j++) {
            float w = W1[(size_t)j * 128 + nn];
            v0 = fmaf(r0[j], w, v0);
            v1 = fmaf(r1[j], w, v1);
        }
        uint32_t lo, hi = packhl(v0, v1, lo);
        int w = widx(m);
        g_whi[0][nn * 64 + w] = hi;
        g_wlo[0][nn * 64 + w] = lo;
    }
    if (blockIdx.x == 0 && threadIdx.x < 128) {
        int nc = threadIdx.x;
        float b = 0.f;
        for (int j = 0; j < 128; j++) b = fmaf(be[j], W1[(size_t)j * 128 + nc], b);
        g_bc[nc] = b;
    }
}

// ---------------------------------------------------------------- x convert
__global__ void k_xconv(const float* __restrict__ x, uint32_t* __restrict__ ohi,
                        uint32_t* __restrict__ olo, int n) {
    int gid = blockIdx.x * blockDim.x + threadIdx.x;   // n * 64
    int node = gid >> 6, m = gid & 63;
    if (node >= n) return;
    float2 v = *reinterpret_cast<const float2*>(&x[(size_t)node * 128 + m * 2]);
    uint32_t lo, hi = packhl(v.x, v.y, lo);
    int w = widx(m);
    ohi[(size_t)node * 64 + w] = hi;
    olo[(size_t)node * 64 + w] = lo;
}

// ---------------------------------------------------------------- mma GEMM
// t16[M,BN] = fp16( (A[M,128] @ W[128,BN] + bias) * dis[row] )
// 3-term bf16 split: AhBh + AlBh + AhBl. Bias is PRE-scale.
template <int BN, bool SCALE, bool BIAS>
__global__ void __launch_bounds__(256, 2)
k_mgemm(const uint32_t* __restrict__ Ahi, const uint32_t* __restrict__ Alo,
        const uint32_t* __restrict__ Whi, const uint32_t* __restrict__ Wlo,
        const float* __restrict__ bias, const float* __restrict__ dis,
        uint32_t* __restrict__ out16, int M)
{
    constexpr int NT = BN / 16;
    __shared__ __align__(16) uint32_t sA[2][2][128 * 8];
    __shared__ __align__(16) uint32_t sW[2][2][BN * 8];

    const int tid  = threadIdx.x;
    const int wid  = tid >> 5, lane = tid & 31;
    const int g    = lane >> 2, t = lane & 3;
    const int wm   = wid & 3, wn = wid >> 2;
    const int row0 = blockIdx.x * 128;

    const uint32_t sAb = sm32(sA);
    const uint32_t sWb = sm32(sW);
    constexpr uint32_t A_P = 128 * 8 * 4;
    constexpr uint32_t W_P = BN * 8 * 4;

    float acc[2][NT][4];
#pragma unroll
    for (int i = 0; i < 2; i++)
#pragma unroll
        for (int j = 0; j < NT; j++)
#pragma unroll
            for (int q = 0; q < 4; q++) acc[i][j][q] = 0.f;

    auto issue = [&](int kt, int buf) {
        int r = tid >> 1, h = tid & 1;
        int gr = row0 + r; if (gr >= M) gr = M - 1;
        uint32_t off = (uint32_t)(r * 8 + h * 4) * 4u;
        uint32_t abase = sAb + (uint32_t)buf * 2u * A_P;
        cpa16(abase + off,       Ahi + (size_t)gr * 64 + kt * 8 + h * 4);
        cpa16(abase + A_P + off, Alo + (size_t)gr * 64 + kt * 8 + h * 4);
        if (tid < BN * 2) {
            uint32_t wbase = sWb + (uint32_t)buf * 2u * W_P;
            uint32_t offw = (uint32_t)(r * 8 + h * 4) * 4u;
            cpa16(wbase + offw,       Whi + r * 64 + kt * 8 + h * 4);
            cpa16(wbase + W_P + offw, Wlo + r * 64 + kt * 8 + h * 4);
        }
        asm volatile("cp.async.commit_group;" ::: "memory");
    };

    issue(0, 0);
    for (int kt = 0; kt < 8; kt++) {
        const int buf = kt & 1;
        if (kt < 7) {
            issue(kt + 1, buf ^ 1);
            asm volatile("cp.async.wait_group 1;" ::: "memory");
        } else {
            asm volatile("cp.async.wait_group 0;" ::: "memory");
        }
        __syncthreads();

        const uint32_t* pAh = sA[buf][0];
        const uint32_t* pAl = sA[buf][1];
        const uint32_t* pWh = sW[buf][0];
        const uint32_t* pWl = sW[buf][1];

        uint32_t ah[2][4], al[2][4];
#pragma unroll
        for (int mt = 0; mt < 2; mt++) {
            int r0 = wm * 32 + mt * 16 + g;
            uint2 v;
            v = *reinterpret_cast<const uint2*>(&pAh[r0 * 8 + t * 2]);
            ah[mt][0] = v.x; ah[mt][2] = v.y;
            v = *reinterpret_cast<const uint2*>(&pAh[(r0 + 8) * 8 + t * 2]);
            ah[mt][1] = v.x; ah[mt][3] = v.y;
            v = *reinterpret_cast<const uint2*>(&pAl[r0 * 8 + t * 2]);
            al[mt][0] = v.x; al[mt][2] = v.y;
            v = *reinterpret_cast<const uint2*>(&pAl[(r0 + 8) * 8 + t * 2]);
            al[mt][1] = v.x; al[mt][3] = v.y;
        }
#pragma unroll
        for (int nt = 0; nt < NT; nt++) {
            int rn = wn * (NT * 8) + nt * 8 + g;
            uint2 bh = *reinterpret_cast<const uint2*>(&pWh[rn * 8 + t * 2]);
            uint2 bl = *reinterpret_cast<const uint2*>(&pWl[rn * 8 + t * 2]);
#pragma unroll
            for (int mt = 0; mt < 2; mt++) {
                MMA_BF16(acc[mt][nt], ah[mt], bh);
                MMA_BF16(acc[mt][nt], al[mt], bh);
                MMA_BF16(acc[mt][nt], ah[mt], bl);
            }
        }
        __syncthreads();
    }

    // ---- epilogue: v = (acc + bias) * dis ----
#pragma unroll
    for (int mt = 0; mt < 2; mt++) {
        int r0 = row0 + wm * 32 + mt * 16 + g;
        int r1 = r0 + 8;
        bool ok0 = r0 < M, ok1 = r1 < M;
        float sc0 = (SCALE && ok0) ? dis[r0] : 1.0f;
        float sc1 = (SCALE && ok1) ? dis[r1] : 1.0f;
#pragma unroll
        for (int nt = 0; nt < NT; nt++) {
            int c = wn * (NT * 8) + nt * 8 + 2 * t;
            float b0 = 0.f, b1 = 0.f;
            if (BIAS) {
                float2 bb = *reinterpret_cast<const float2*>(&bias[c]);
                b0 = bb.x; b1 = bb.y;
            }
            float v00 = (acc[mt][nt][0] + b0) * sc0;
            float v01 = (acc[mt][nt][1] + b1) * sc0;
            float v10 = (acc[mt][nt][2] + b0) * sc1;
            float v11 = (acc[mt][nt][3] + b1) * sc1;
            if (ok0) out16[(size_t)r0 * (BN / 2) + (c >> 1)] = packh2(v00, v01);
            if (ok1) out16[(size_t)r1 * (BN / 2) + (c >> 1)] = packh2(v10, v11);
        }
    }
}

// ---------------------------------------------------------------- aggregation
// One warp per dst node; tb16 holds half2-packed GEMM output.
// COLS==128: emit bf16 hi/lo for the next GEMM. COLS==64: fused pool via red.v2.
template <int COLS, bool RELU>
__global__ void k_agg(const uint32_t* __restrict__ tb16, const int* __restrict__ rowptr,
                      const int* __restrict__ esrc, const float* __restrict__ dis,
                      const float* __restrict__ bias, uint32_t* __restrict__ ohi,
                      uint32_t* __restrict__ olo, const int* __restrict__ batch,
                      float* __restrict__ dout, int n) {
    const int warp = (blockIdx.x * blockDim.x + threadIdx.x) >> 5;
    const int lane = threadIdx.x & 31;
    if (warp >= n) return;
    const int beg = __ldg(&rowptr[warp]);
    const int end = __ldg(&rowptr[warp + 1]);

    if constexpr (COLS == 128) {
        uint2 sv = *reinterpret_cast<const uint2*>(&tb16[(size_t)warp * 64 + lane * 2]);
        float2 a0 = unph2(sv.x), a1 = unph2(sv.y);
        float4 acc = make_float4(a0.x, a0.y, a1.x, a1.y);
        int e = beg;
        for (; e + 8 <= end; e += 8) {
            int s[8];
#pragma unroll
            for (int u = 0; u < 8; u++) s[u] = __ldg(&esrc[e + u]);
            uint2 v[8];
#pragma unroll
            for (int u = 0; u < 8; u++)
                v[u] = *reinterpret_cast<const uint2*>(&tb16[(size_t)s[u] * 64 + lane * 2]);
#pragma unroll
            for (int u = 0; u < 8; u++) {
                float2 f0 = unph2(v[u].x), f1 = unph2(v[u].y);
                acc.x += f0.x; acc.y += f0.y; acc.z += f1.x; acc.w += f1.y;
            }
        }
        for (; e < end; e++) {
            int s = __ldg(&esrc[e]);
            uint2 v = *reinterpret_cast<const uint2*>(&tb16[(size_t)s * 64 + lane * 2]);
            float2 f0 = unph2(v.x), f1 = unph2(v.y);
            acc.x += f0.x; acc.y += f0.y; acc.z += f1.x; acc.w += f1.y;
        }
        float d = dis[warp];
        float4 b = *reinterpret_cast<const float4*>(&bias[lane * 4]);
        float4 r;
        r.x = fmaf(acc.x, d, b.x);
        r.y = fmaf(acc.y, d, b.y);
        r.z = fmaf(acc.z, d, b.z);
        r.w = fmaf(acc.w, d, b.w);
        if (RELU) {
            r.x = fmaxf(r.x, 0.f); r.y = fmaxf(r.y, 0.f);
            r.z = fmaxf(r.z, 0.f); r.w = fmaxf(r.w, 0.f);
        }
        int m0 = lane * 2;
        int w0 = widx(m0), w1 = widx(m0 + 1);
        uint32_t lo0, hi0 = packhl(r.x, r.y, lo0);
        uint32_t lo1, hi1 = packhl(r.z, r.w, lo1);
        ohi[(size_t)warp * 64 + w0] = hi0;
        olo[(size_t)warp * 64 + w0] = lo0;
        ohi[(size_t)warp * 64 + w1] = hi1;
        olo[(size_t)warp * 64 + w1] = lo1;
    } else {  // COLS == 64: fused pool
        float2 acc = unph2(tb16[(size_t)warp * 32 + lane]);
        int e = beg;
        for (; e + 8 <= end; e += 8) {
            int s[8];
#pragma unroll
            for (int u = 0; u < 8; u++) s[u] = __ldg(&esrc[e + u]);
            uint32_t v[8];
#pragma unroll
            for (int u = 0; u < 8; u++) v[u] = tb16[(size_t)s[u] * 32 + lane];
#pragma unroll
            for (int u = 0; u < 8; u++) {
                float2 f = unph2(v[u]);
                acc.x += f.x; acc.y += f.y;
            }
        }
        for (; e < end; e++) {
            int s = __ldg(&esrc[e]);
            float2 f = unph2(tb16[(size_t)s * 32 + lane]);
            acc.x += f.x; acc.y += f.y;
        }
        float d = dis[warp];
        float2 b = *reinterpret_cast<const float2*>(&bias[lane * 2]);
        float rx = fmaf(acc.x, d, b.x);
        float ry = fmaf(acc.y, d, b.y);
        int gidx = __ldg(&batch[warp]);
        float* a = &dout[(size_t)gidx * 64 + lane * 2];
        asm volatile("red.global.add.v2.f32 [%0], {%1,%2};"
                     :: "l"(a), "f"(rx), "f"(ry) : "memory");
    }
}

// ---------------------------------------------------------------- launch
extern "C" void kernel_launch(void* const* d_in, const int* in_sizes, int n_in,
                              void* d_out, int out_size) {
    const float* x     = (const float*)d_in[0];
    const int*   ei    = (const int*)  d_in[1];
    const int*   batch = (const int*)  d_in[2];
    const float* W_emb = (const float*)d_in[3];
    const float* b_emb = (const float*)d_in[4];
    const float* W1    = (const float*)d_in[5];
    const float* b1    = (const float*)d_in[6];
    const float* W2    = (const float*)d_in[7];
    const float* b2    = (const float*)d_in[8];
    const float* W3    = (const float*)d_in[9];
    const float* b3    = (const float*)d_in[10];

    const int n = in_sizes[2];
    const int e = in_sizes[1] / 2;
    const int* src = ei;
    const int* dst = ei + e;

    float *dis, *bc;
    int *rowptr, *esrc;
    uint32_t *t16, *ahi, *alo, *bhi, *blo, *whi, *wlo;
    cudaGetSymbolAddress((void**)&dis,    g_dis);
    cudaGetSymbolAddress((void**)&bc,     g_bc);
    cudaGetSymbolAddress((void**)&rowptr, g_rowptr);
    cudaGetSymbolAddress((void**)&esrc,   g_esrc);
    cudaGetSymbolAddress((void**)&t16,    g_t16);
    cudaGetSymbolAddress((void**)&ahi,    g_ahi);
    cudaGetSymbolAddress((void**)&alo,    g_alo);
    cudaGetSymbolAddress((void**)&bhi,    g_bhi);
    cudaGetSymbolAddress((void**)&blo,    g_blo);
    cudaGetSymbolAddress((void**)&whi,    g_whi);
    cudaGetSymbolAddress((void**)&wlo,    g_wlo);

    auto cdiv = [](long long a, long long b) { return (int)((a + b - 1) / b); };

    // 0: fused prep (CSR + dis + zero d_out)
    k_prep<<<PREP_BLOCKS, PREP_THREADS>>>(src, dst, e, n, (float*)d_out, out_size / 4);
    // 1: W2/W3 images
    k_wprep<<<cdiv(2 * 8192, 256), 256>>>(W2, W3);
    // 2: combined Wc = W_emb@W1 image (slot 0) + bc = b_emb@W1
    k_wcomb<<<32, 256>>>(W_emb, W1, b_emb);
    // 3: x -> bf16 hi/lo
    k_xconv<<<cdiv((long long)n * 64, 256), 256>>>(x, ahi, alo, n);
    // 4: layer-1 GEMM (folded embedding)  t16 = fp16((x@Wc + bc) * dis)
    k_mgemm<128, true, true><<<cdiv(n, 128), 256>>>(
        ahi, alo, whi + 0 * 8192, wlo + 0 * 8192, bc, dis, t16, n);
    // 5: layer-1 agg -> bf16 (B set)
    k_agg<128, true><<<cdiv(n, 8), 256>>>(t16, rowptr, esrc, dis, b1, bhi, blo,
                                          nullptr, nullptr, n);
    // 6-7: layer 2
    k_mgemm<128, true, false><<<cdiv(n, 128), 256>>>(
        bhi, blo, whi + 2 * 8192, wlo + 2 * 8192, nullptr, dis, t16, n);
    k_agg<128, true><<<cdiv(n, 8), 256>>>(t16, rowptr, esrc, dis, b2, ahi, alo,
                                          nullptr, nullptr, n);
    // 8-9: layer 3 (BN = 64, no relu) + fused pool
    k_mgemm<64, true, false><<<cdiv(n, 128), 256>>>(
        ahi, alo, whi + 3 * 8192, wlo + 3 * 8192, nullptr, dis, t16, n);
    k_agg<64, false><<<cdiv(n, 8), 256>>>(t16, rowptr, esrc, dis, b3, nullptr, nullptr,
                                          batch, (float*)d_out, n);
}

// round 10
// speedup vs baseline: 1.8744x; 1.1564x over previous
#include <cuda_runtime.h>
#include <cuda_fp16.h>
#include <cstdint>

#define NMAX  100000
#define EMAX  1600000
#define PREP_BLOCKS 128
#define PREP_THREADS 1024

// ---------------------------------------------------------------- scratch
__device__ float    g_dis[NMAX];
__device__ int      g_deg [NMAX];
__device__ int      g_rowptr[NMAX + 1];
__device__ int      g_cursor[NMAX];
__device__ int      g_esrc[EMAX];
__device__ uint32_t g_t16[NMAX * 64];      // GEMM output as half2 pairs (agg input)
__device__ uint32_t g_a16[NMAX * 64];      // fp16 activations (A set, k-permuted)
__device__ uint32_t g_b16[NMAX * 64];      // fp16 activations (B set, k-permuted)
__device__ uint32_t g_whi[4][8192], g_wlo[4][8192];  // fp16 hi/lo W^T images
__device__ float    g_bc[128];             // b_emb @ W1
__device__ int      g_bsum[PREP_BLOCKS];
__device__ int      g_boff[PREP_BLOCKS];
__device__ int      g_total;
__device__ unsigned g_bar;

// ---------------------------------------------------------------- helpers
__device__ __forceinline__ uint32_t sm32(const void* p) {
    uint32_t a;
    asm("{ .reg .u64 t; cvta.to.shared.u64 t, %1; cvt.u32.u64 %0, t; }" : "=r"(a) : "l"(p));
    return a;
}
__device__ __forceinline__ void cpa16(uint32_t dst, const void* src) {
    asm volatile("cp.async.cg.shared.global [%0], [%1], 16;" :: "r"(dst), "l"(src));
}
__device__ __forceinline__ uint32_t packh2(float v0, float v1) {
    __half2 h = __floats2half2_rn(v0, v1);
    return *reinterpret_cast<uint32_t*>(&h);
}
__device__ __forceinline__ float2 unph2(uint32_t u) {
    return __half22float2(*reinterpret_cast<__half2*>(&u));
}
// fp16 hi/lo split of (v0, v1)
__device__ __forceinline__ uint32_t packh2hl(float v0, float v1, uint32_t& lo) {
    __half2 h = __floats2half2_rn(v0, v1);
    uint32_t hb = *reinterpret_cast<uint32_t*>(&h);
    float2 hf = __half22float2(h);
    __half2 l = __floats2half2_rn(v0 - hf.x, v1 - hf.y);
    lo = *reinterpret_cast<uint32_t*>(&l);
    return hb;
}
// k-pair permuted uint index within a 64-uint (128 half) row, m = k-pair index 0..63
__device__ __forceinline__ int widx(int m) {
    int mg = m & 7;
    return ((m >> 3) << 3) + ((mg & 3) << 1) + (mg >> 2);
}
#define MMA_F16(d, a, b) \
    asm volatile("mma.sync.aligned.m16n8k16.row.col.f32.f16.f16.f32 " \
        "{%0,%1,%2,%3}, {%4,%5,%6,%7}, {%8,%9}, {%0,%1,%2,%3};" \
        : "+f"((d)[0]), "+f"((d)[1]), "+f"((d)[2]), "+f"((d)[3]) \
        : "r"((a)[0]), "r"((a)[1]), "r"((a)[2]), "r"((a)[3]), "r"((b).x), "r"((b).y))

// ---------------------------------------------------------------- grid sync
__device__ __forceinline__ void grid_sync(int nb) {
    __syncthreads();
    if (threadIdx.x == 0) {
        __threadfence();
        unsigned ticket = atomicAdd(&g_bar, 1u);
        unsigned phase  = ticket / (unsigned)nb + 1u;
        while (atomicAdd(&g_bar, 0u) < phase * (unsigned)nb) { }
    }
    __syncthreads();
}

// ---------------------------------------------------------------- fused prep
__global__ __launch_bounds__(PREP_THREADS, 1)
void k_prep(const int* __restrict__ src, const int* __restrict__ dst, int e, int n,
            float* __restrict__ d_out, int out4) {
    const int tid  = threadIdx.x;
    const int lane = tid & 31, wid = tid >> 5;
    const int T    = PREP_BLOCKS * PREP_THREADS;
    const int gtid = blockIdx.x * PREP_THREADS + tid;
    __shared__ int sh[32];
    __shared__ int s_boff;

    for (int i = gtid; i < n; i += T) g_deg[i] = 0;
    float4* o4 = reinterpret_cast<float4*>(d_out);
    for (int i = gtid; i < out4; i += T) o4[i] = make_float4(0.f, 0.f, 0.f, 0.f);
    grid_sync(PREP_BLOCKS);

    for (int i = gtid; i < e; i += T) atomicAdd(&g_deg[dst[i]], 1);
    grid_sync(PREP_BLOCKS);

    for (int i = gtid; i < n; i += T) g_dis[i] = rsqrtf((float)g_deg[i] + 1.0f);

    const int per = (n + T - 1) / T;
    const int cb  = gtid * per;
    const int ce  = min(cb + per, n);
    int csum = 0;
    for (int i = cb; i < ce; i++) csum += g_deg[i];

    int x = csum;
#pragma unroll
    for (int o = 1; o < 32; o <<= 1) {
        int y = __shfl_up_sync(0xffffffffu, x, o);
        if (lane >= o) x += y;
    }
    if (lane == 31) sh[wid] = x;
    __syncthreads();
    if (wid == 0) {
        int w = sh[lane];
        int xx = w;
#pragma unroll
        for (int o = 1; o < 32; o <<= 1) {
            int y = __shfl_up_sync(0xffffffffu, xx, o);
            if (lane >= o) xx += y;
        }
        sh[lane] = xx - w;
        if (lane == 31) g_bsum[blockIdx.x] = xx;
    }
    __syncthreads();
    const int thr_excl = x - csum + sh[wid];
    grid_sync(PREP_BLOCKS);

    if (blockIdx.x == 0 && wid == 0) {
        int carry = 0;
        for (int base = 0; base < PREP_BLOCKS; base += 32) {
            int v = g_bsum[base + lane];
            int s = v;
#pragma unroll
            for (int o = 1; o < 32; o <<= 1) {
                int y = __shfl_up_sync(0xffffffffu, s, o);
                if (lane >= o) s += y;
            }
            g_boff[base + lane] = s - v + carry;
            carry += __shfl_sync(0xffffffffu, s, 31);
        }
        if (lane == 0) g_total = carry;
    }
    grid_sync(PREP_BLOCKS);

    if (tid == 0) s_boff = g_boff[blockIdx.x];
    __syncthreads();
    int run = s_boff + thr_excl;
    for (int i = cb; i < ce; i++) {
        g_rowptr[i] = run;
        g_cursor[i] = run;
        run += g_deg[i];
    }
    if (gtid == 0) g_rowptr[n] = g_total;
    grid_sync(PREP_BLOCKS);

    for (int i = gtid; i < e; i += T) {
        int pos = atomicAdd(&g_cursor[dst[i]], 1);
        g_esrc[pos] = src[i];
    }
}

// ---------------------------------------------------------------- weight prep
// Images for W2 (slot 2) and W3 (slot 3); slot 0 built by k_wcomb.
__global__ void k_wprep(const float* __restrict__ W2, const float* __restrict__ W3) {
    int gid = blockIdx.x * blockDim.x + threadIdx.x;   // 2 * 8192
    int L   = 2 + (gid >> 13);
    int idx = gid & 8191;
    if (L > 3) return;
    int N = (L == 3) ? 64 : 128;
    int nn = idx >> 6, m = idx & 63;
    if (nn >= N) return;
    const float* W = (L == 2) ? W2 : W3;
    float v0 = W[(size_t)(2 * m) * N + nn];
    float v1 = W[(size_t)(2 * m + 1) * N + nn];
    uint32_t lo, hi = packh2hl(v0, v1, lo);
    int w = widx(m);
    g_whi[L][nn * 64 + w] = hi;
    g_wlo[L][nn * 64 + w] = lo;
}

// ---------------------------------------------------------------- combined weight
// Wc = W_emb @ W1 (128x128, fp32), fp16 hi/lo into slot 0; bc = b_emb @ W1.
__global__ void k_wcomb(const float* __restrict__ We, const float* __restrict__ W1,
                        const float* __restrict__ be) {
    int gid = blockIdx.x * blockDim.x + threadIdx.x;   // 8192
    int m = gid >> 7, nn = gid & 127;
    if (m < 64) {
        float v0 = 0.f, v1 = 0.f;
        const float* r0 = &We[(size_t)(2 * m) * 128];
        const float* r1 = &We[(size_t)(2 * m + 1) * 128];
#pragma unroll 4
        for (int j = 0; j < 128; j++) {
            float w = W1[(size_t)j * 128 + nn];
            v0 = fmaf(r0[j], w, v0);
            v1 = fmaf(r1[j], w, v1);
        }
        uint32_t lo, hi = packh2hl(v0, v1, lo);
        int w = widx(m);
        g_whi[0][nn * 64 + w] = hi;
        g_wlo[0][nn * 64 + w] = lo;
    }
    if (blockIdx.x == 0 && threadIdx.x < 128) {
        int nc = threadIdx.x;
        float b = 0.f;
        for (int j = 0; j < 128; j++) b = fmaf(be[j], W1[(size_t)j * 128 + nc], b);
        g_bc[nc] = b;
    }
}

// ---------------------------------------------------------------- x convert
__global__ void k_xconv(const float* __restrict__ x, uint32_t* __restrict__ o16, int n) {
    int gid = blockIdx.x * blockDim.x + threadIdx.x;   // n * 64
    int node = gid >> 6, m = gid & 63;
    if (node >= n) return;
    float2 v = *reinterpret_cast<const float2*>(&x[(size_t)node * 128 + m * 2]);
    o16[(size_t)node * 64 + widx(m)] = packh2(v.x, v.y);
}

// ---------------------------------------------------------------- mma GEMM
// t16[M,BN] = fp16( (A[M,128] @ W[128,BN] + bias) * dis[row] )
// A: fp16 single plane (k-permuted). W: fp16 hi/lo. 2-term: A*Wh + A*Wl.
template <int BN, bool SCALE, bool BIAS>
__global__ void __launch_bounds__(256, 2)
k_mgemm(const uint32_t* __restrict__ A16,
        const uint32_t* __restrict__ Whi, const uint32_t* __restrict__ Wlo,
        const float* __restrict__ bias, const float* __restrict__ dis,
        uint32_t* __restrict__ out16, int M)
{
    constexpr int NT = BN / 16;
    __shared__ __align__(16) uint32_t sA[2][128 * 8];
    __shared__ __align__(16) uint32_t sW[2][2][BN * 8];

    const int tid  = threadIdx.x;
    const int wid  = tid >> 5, lane = tid & 31;
    const int g    = lane >> 2, t = lane & 3;
    const int wm   = wid & 3, wn = wid >> 2;
    const int row0 = blockIdx.x * 128;

    const uint32_t sAb = sm32(sA);
    const uint32_t sWb = sm32(sW);
    constexpr uint32_t A_P = 128 * 8 * 4;
    constexpr uint32_t W_P = BN * 8 * 4;

    float acc[2][NT][4];
#pragma unroll
    for (int i = 0; i < 2; i++)
#pragma unroll
        for (int j = 0; j < NT; j++)
#pragma unroll
            for (int q = 0; q < 4; q++) acc[i][j][q] = 0.f;

    auto issue = [&](int kt, int buf) {
        int r = tid >> 1, h = tid & 1;
        int gr = row0 + r; if (gr >= M) gr = M - 1;
        uint32_t off = (uint32_t)(r * 8 + h * 4) * 4u;
        cpa16(sAb + (uint32_t)buf * A_P + off, A16 + (size_t)gr * 64 + kt * 8 + h * 4);
        if (tid < BN * 2) {
            uint32_t wbase = sWb + (uint32_t)buf * 2u * W_P;
            cpa16(wbase + off,       Whi + r * 64 + kt * 8 + h * 4);
            cpa16(wbase + W_P + off, Wlo + r * 64 + kt * 8 + h * 4);
        }
        asm volatile("cp.async.commit_group;" ::: "memory");
    };

    issue(0, 0);
    for (int kt = 0; kt < 8; kt++) {
        const int buf = kt & 1;
        if (kt < 7) {
            issue(kt + 1, buf ^ 1);
            asm volatile("cp.async.wait_group 1;" ::: "memory");
        } else {
            asm volatile("cp.async.wait_group 0;" ::: "memory");
        }
        __syncthreads();

        const uint32_t* pA  = sA[buf];
        const uint32_t* pWh = sW[buf][0];
        const uint32_t* pWl = sW[buf][1];

        uint32_t a[2][4];
#pragma unroll
        for (int mt = 0; mt < 2; mt++) {
            int r0 = wm * 32 + mt * 16 + g;
            uint2 v;
            v = *reinterpret_cast<const uint2*>(&pA[r0 * 8 + t * 2]);
            a[mt][0] = v.x; a[mt][2] = v.y;
            v = *reinterpret_cast<const uint2*>(&pA[(r0 + 8) * 8 + t * 2]);
            a[mt][1] = v.x; a[mt][3] = v.y;
        }
#pragma unroll
        for (int nt = 0; nt < NT; nt++) {
            int rn = wn * (NT * 8) + nt * 8 + g;
            uint2 bh = *reinterpret_cast<const uint2*>(&pWh[rn * 8 + t * 2]);
            uint2 bl = *reinterpret_cast<const uint2*>(&pWl[rn * 8 + t * 2]);
#pragma unroll
            for (int mt = 0; mt < 2; mt++) {
                MMA_F16(acc[mt][nt], a[mt], bh);
                MMA_F16(acc[mt][nt], a[mt], bl);
            }
        }
        __syncthreads();
    }

    // ---- epilogue: v = (acc + bias) * dis ----
#pragma unroll
    for (int mt = 0; mt < 2; mt++) {
        int r0 = row0 + wm * 32 + mt * 16 + g;
        int r1 = r0 + 8;
        bool ok0 = r0 < M, ok1 = r1 < M;
        float sc0 = (SCALE && ok0) ? dis[r0] : 1.0f;
        float sc1 = (SCALE && ok1) ? dis[r1] : 1.0f;
#pragma unroll
        for (int nt = 0; nt < NT; nt++) {
            int c = wn * (NT * 8) + nt * 8 + 2 * t;
            float b0 = 0.f, b1 = 0.f;
            if (BIAS) {
                float2 bb = *reinterpret_cast<const float2*>(&bias[c]);
                b0 = bb.x; b1 = bb.y;
            }
            float v00 = (acc[mt][nt][0] + b0) * sc0;
            float v01 = (acc[mt][nt][1] + b1) * sc0;
            float v10 = (acc[mt][nt][2] + b0) * sc1;
            float v11 = (acc[mt][nt][3] + b1) * sc1;
            if (ok0) out16[(size_t)r0 * (BN / 2) + (c >> 1)] = packh2(v00, v01);
            if (ok1) out16[(size_t)r1 * (BN / 2) + (c >> 1)] = packh2(v10, v11);
        }
    }
}

// ---------------------------------------------------------------- aggregation
// One warp per dst node; tb16 holds half2-packed GEMM output.
// COLS==128: emit fp16 single plane (k-permuted) for the next GEMM.
// COLS==64: fused pool via red.global.add.v2.f32.
template <int COLS, bool RELU>
__global__ void k_agg(const uint32_t* __restrict__ tb16, const int* __restrict__ rowptr,
                      const int* __restrict__ esrc, const float* __restrict__ dis,
                      const float* __restrict__ bias, uint32_t* __restrict__ o16,
                      const int* __restrict__ batch, float* __restrict__ dout, int n) {
    const int warp = (blockIdx.x * blockDim.x + threadIdx.x) >> 5;
    const int lane = threadIdx.x & 31;
    if (warp >= n) return;
    const int beg = __ldg(&rowptr[warp]);
    const int end = __ldg(&rowptr[warp + 1]);

    if constexpr (COLS == 128) {
        uint2 sv = *reinterpret_cast<const uint2*>(&tb16[(size_t)warp * 64 + lane * 2]);
        float2 a0 = unph2(sv.x), a1 = unph2(sv.y);
        float4 acc = make_float4(a0.x, a0.y, a1.x, a1.y);
        int e = beg;
        for (; e + 8 <= end; e += 8) {
            int s[8];
#pragma unroll
            for (int u = 0; u < 8; u++) s[u] = __ldg(&esrc[e + u]);
            uint2 v[8];
#pragma unroll
            for (int u = 0; u < 8; u++)
                v[u] = *reinterpret_cast<const uint2*>(&tb16[(size_t)s[u] * 64 + lane * 2]);
#pragma unroll
            for (int u = 0; u < 8; u++) {
                float2 f0 = unph2(v[u].x), f1 = unph2(v[u].y);
                acc.x += f0.x; acc.y += f0.y; acc.z += f1.x; acc.w += f1.y;
            }
        }
        for (; e < end; e++) {
            int s = __ldg(&esrc[e]);
            uint2 v = *reinterpret_cast<const uint2*>(&tb16[(size_t)s * 64 + lane * 2]);
            float2 f0 = unph2(v.x), f1 = unph2(v.y);
            acc.x += f0.x; acc.y += f0.y; acc.z += f1.x; acc.w += f1.y;
        }
        float d = dis[warp];
        float4 b = *reinterpret_cast<const float4*>(&bias[lane * 4]);
        float4 r;
        r.x = fmaf(acc.x, d, b.x);
        r.y = fmaf(acc.y, d, b.y);
        r.z = fmaf(acc.z, d, b.z);
        r.w = fmaf(acc.w, d, b.w);
        if (RELU) {
            r.x = fmaxf(r.x, 0.f); r.y = fmaxf(r.y, 0.f);
            r.z = fmaxf(r.z, 0.f); r.w = fmaxf(r.w, 0.f);
        }
        int m0 = lane * 2;
        o16[(size_t)warp * 64 + widx(m0)]     = packh2(r.x, r.y);
        o16[(size_t)warp * 64 + widx(m0 + 1)] = packh2(r.z, r.w);
    } else {  // COLS == 64: fused pool
        float2 acc = unph2(tb16[(size_t)warp * 32 + lane]);
        int e = beg;
        for (; e + 8 <= end; e += 8) {
            int s[8];
#pragma unroll
            for (int u = 0; u < 8; u++) s[u] = __ldg(&esrc[e + u]);
            uint32_t v[8];
#pragma unroll
            for (int u = 0; u < 8; u++) v[u] = tb16[(size_t)s[u] * 32 + lane];
#pragma unroll
            for (int u = 0; u < 8; u++) {
                float2 f = unph2(v[u]);
                acc.x += f.x; acc.y += f.y;
            }
        }
        for (; e < end; e++) {
            int s = __ldg(&esrc[e]);
            float2 f = unph2(tb16[(size_t)s * 32 + lane]);
            acc.x += f.x; acc.y += f.y;
        }
        float d = dis[warp];
        float2 b = *reinterpret_cast<const float2*>(&bias[lane * 2]);
        float rx = fmaf(acc.x, d, b.x);
        float ry = fmaf(acc.y, d, b.y);
        int gidx = __ldg(&batch[warp]);
        float* a = &dout[(size_t)gidx * 64 + lane * 2];
        asm volatile("red.global.add.v2.f32 [%0], {%1,%2};"
                     :: "l"(a), "f"(rx), "f"(ry) : "memory");
    }
}

// ---------------------------------------------------------------- launch
extern "C" void kernel_launch(void* const* d_in, const int* in_sizes, int n_in,
                              void* d_out, int out_size) {
    const float* x     = (const float*)d_in[0];
    const int*   ei    = (const int*)  d_in[1];
    const int*   batch = (const int*)  d_in[2];
    const float* W_emb = (const float*)d_in[3];
    const float* b_emb = (const float*)d_in[4];
    const float* W1    = (const float*)d_in[5];
    const float* b1    = (const float*)d_in[6];
    const float* W2    = (const float*)d_in[7];
    const float* b2    = (const float*)d_in[8];
    const float* W3    = (const float*)d_in[9];
    const float* b3    = (const float*)d_in[10];

    const int n = in_sizes[2];
    const int e = in_sizes[1] / 2;
    const int* src = ei;
    const int* dst = ei + e;

    float *dis, *bc;
    int *rowptr, *esrc;
    uint32_t *t16, *a16, *b16, *whi, *wlo;
    cudaGetSymbolAddress((void**)&dis,    g_dis);
    cudaGetSymbolAddress((void**)&bc,     g_bc);
    cudaGetSymbolAddress((void**)&rowptr, g_rowptr);
    cudaGetSymbolAddress((void**)&esrc,   g_esrc);
    cudaGetSymbolAddress((void**)&t16,    g_t16);
    cudaGetSymbolAddress((void**)&a16,    g_a16);
    cudaGetSymbolAddress((void**)&b16,    g_b16);
    cudaGetSymbolAddress((void**)&whi,    g_whi);
    cudaGetSymbolAddress((void**)&wlo,    g_wlo);

    auto cdiv = [](long long a, long long b) { return (int)((a + b - 1) / b); };

    // 0: fused prep (CSR + dis + zero d_out)
    k_prep<<<PREP_BLOCKS, PREP_THREADS>>>(src, dst, e, n, (float*)d_out, out_size / 4);
    // 1: W2/W3 images
    k_wprep<<<cdiv(2 * 8192, 256), 256>>>(W2, W3);
    // 2: combined Wc = W_emb@W1 image (slot 0) + bc = b_emb@W1
    k_wcomb<<<32, 256>>>(W_emb, W1, b_emb);
    // 3: x -> fp16
    k_xconv<<<cdiv((long long)n * 64, 256), 256>>>(x, a16, n);
    // 4: layer-1 GEMM (folded embedding)  t16 = fp16((x@Wc + bc) * dis)
    k_mgemm<128, true, true><<<cdiv(n, 128), 256>>>(
        a16, whi + 0 * 8192, wlo + 0 * 8192, bc, dis, t16, n);
    // 5: layer-1 agg -> fp16 (B set)
    k_agg<128, true><<<cdiv(n, 8), 256>>>(t16, rowptr, esrc, dis, b1, b16,
                                          nullptr, nullptr, n);
    // 6-7: layer 2
    k_mgemm<128, true, false><<<cdiv(n, 128), 256>>>(
        b16, whi + 2 * 8192, wlo + 2 * 8192, nullptr, dis, t16, n);
    k_agg<128, true><<<cdiv(n, 8), 256>>>(t16, rowptr, esrc, dis, b2, a16,
                                          nullptr, nullptr, n);
    // 8-9: layer 3 (BN = 64, no relu) + fused pool
    k_mgemm<64, true, false><<<cdiv(n, 128), 256>>>(
        a16, whi + 3 * 8192, wlo + 3 * 8192, nullptr, dis, t16, n);
    k_agg<64, false><<<cdiv(n, 8), 256>>>(t16, rowptr, esrc, dis, b3, nullptr,
                                          batch, (float*)d_out, n);
}

// round 11
// speedup vs baseline: 1.8929x; 1.0099x over previous
#include <cuda_runtime.h>
#include <cuda_fp16.h>
#include <cstdint>

#define NMAX  100000
#define EMAX  1600000
#define PREP_BLOCKS 128
#define PREP_THREADS 1024

// ---------------------------------------------------------------- scratch
__device__ float    g_dis[NMAX];
__device__ int      g_deg [NMAX];
__device__ int      g_rowptr[NMAX + 1];
__device__ int      g_cursor[NMAX];
__device__ int      g_esrc[EMAX];
__device__ uint32_t g_t16[NMAX * 64];      // GEMM output as half2 pairs (agg input)
__device__ uint32_t g_a16[NMAX * 64];      // fp16 activations (A set, k-permuted)
__device__ uint32_t g_b16[NMAX * 64];      // fp16 activations (B set, k-permuted)
__device__ uint32_t g_whi[4][8192], g_wlo[4][8192];  // fp16 hi/lo W^T images
__device__ float    g_bc[128];             // b_emb @ W1
__device__ int      g_bsum[PREP_BLOCKS];
__device__ int      g_boff[PREP_BLOCKS];
__device__ int      g_total;
__device__ unsigned g_bar;

// ---------------------------------------------------------------- helpers
__device__ __forceinline__ uint32_t sm32(const void* p) {
    uint32_t a;
    asm("{ .reg .u64 t; cvta.to.shared.u64 t, %1; cvt.u32.u64 %0, t; }" : "=r"(a) : "l"(p));
    return a;
}
__device__ __forceinline__ void cpa16(uint32_t dst, const void* src) {
    asm volatile("cp.async.cg.shared.global [%0], [%1], 16;" :: "r"(dst), "l"(src));
}
__device__ __forceinline__ uint32_t packh2(float v0, float v1) {
    __half2 h = __floats2half2_rn(v0, v1);
    return *reinterpret_cast<uint32_t*>(&h);
}
__device__ __forceinline__ float2 unph2(uint32_t u) {
    return __half22float2(*reinterpret_cast<__half2*>(&u));
}
// fp16 hi/lo split of (v0, v1)
__device__ __forceinline__ uint32_t packh2hl(float v0, float v1, uint32_t& lo) {
    __half2 h = __floats2half2_rn(v0, v1);
    uint32_t hb = *reinterpret_cast<uint32_t*>(&h);
    float2 hf = __half22float2(h);
    __half2 l = __floats2half2_rn(v0 - hf.x, v1 - hf.y);
    lo = *reinterpret_cast<uint32_t*>(&l);
    return hb;
}
// k-pair permuted uint index within a 64-uint (128 half) row, m = k-pair index 0..63
__device__ __forceinline__ int widx(int m) {
    int mg = m & 7;
    return ((m >> 3) << 3) + ((mg & 3) << 1) + (mg >> 2);
}
#define MMA_F16(d, a, b) \
    asm volatile("mma.sync.aligned.m16n8k16.row.col.f32.f16.f16.f32 " \
        "{%0,%1,%2,%3}, {%4,%5,%6,%7}, {%8,%9}, {%0,%1,%2,%3};" \
        : "+f"((d)[0]), "+f"((d)[1]), "+f"((d)[2]), "+f"((d)[3]) \
        : "r"((a)[0]), "r"((a)[1]), "r"((a)[2]), "r"((a)[3]), "r"((b).x), "r"((b).y))

// ---------------------------------------------------------------- grid sync
__device__ __forceinline__ void grid_sync(int nb) {
    __syncthreads();
    if (threadIdx.x == 0) {
        __threadfence();
        unsigned ticket = atomicAdd(&g_bar, 1u);
        unsigned phase  = ticket / (unsigned)nb + 1u;
        while (atomicAdd(&g_bar, 0u) < phase * (unsigned)nb) { }
    }
    __syncthreads();
}

// ---------------------------------------------------------------- fused prep
__global__ __launch_bounds__(PREP_THREADS, 1)
void k_prep(const int* __restrict__ src, const int* __restrict__ dst, int e, int n,
            float* __restrict__ d_out, int out4) {
    const int tid  = threadIdx.x;
    const int lane = tid & 31, wid = tid >> 5;
    const int T    = PREP_BLOCKS * PREP_THREADS;
    const int gtid = blockIdx.x * PREP_THREADS + tid;
    __shared__ int sh[32];
    __shared__ int s_boff;

    for (int i = gtid; i < n; i += T) g_deg[i] = 0;
    float4* o4 = reinterpret_cast<float4*>(d_out);
    for (int i = gtid; i < out4; i += T) o4[i] = make_float4(0.f, 0.f, 0.f, 0.f);
    grid_sync(PREP_BLOCKS);

    for (int i = gtid; i < e; i += T) atomicAdd(&g_deg[dst[i]], 1);
    grid_sync(PREP_BLOCKS);

    for (int i = gtid; i < n; i += T) g_dis[i] = rsqrtf((float)g_deg[i] + 1.0f);

    const int per = (n + T - 1) / T;
    const int cb  = gtid * per;
    const int ce  = min(cb + per, n);
    int csum = 0;
    for (int i = cb; i < ce; i++) csum += g_deg[i];

    int x = csum;
#pragma unroll
    for (int o = 1; o < 32; o <<= 1) {
        int y = __shfl_up_sync(0xffffffffu, x, o);
        if (lane >= o) x += y;
    }
    if (lane == 31) sh[wid] = x;
    __syncthreads();
    if (wid == 0) {
        int w = sh[lane];
        int xx = w;
#pragma unroll
        for (int o = 1; o < 32; o <<= 1) {
            int y = __shfl_up_sync(0xffffffffu, xx, o);
            if (lane >= o) xx += y;
        }
        sh[lane] = xx - w;
        if (lane == 31) g_bsum[blockIdx.x] = xx;
    }
    __syncthreads();
    const int thr_excl = x - csum + sh[wid];
    grid_sync(PREP_BLOCKS);

    if (blockIdx.x == 0 && wid == 0) {
        int carry = 0;
        for (int base = 0; base < PREP_BLOCKS; base += 32) {
            int v = g_bsum[base + lane];
            int s = v;
#pragma unroll
            for (int o = 1; o < 32; o <<= 1) {
                int y = __shfl_up_sync(0xffffffffu, s, o);
                if (lane >= o) s += y;
            }
            g_boff[base + lane] = s - v + carry;
            carry += __shfl_sync(0xffffffffu, s, 31);
        }
        if (lane == 0) g_total = carry;
    }
    grid_sync(PREP_BLOCKS);

    if (tid == 0) s_boff = g_boff[blockIdx.x];
    __syncthreads();
    int run = s_boff + thr_excl;
    for (int i = cb; i < ce; i++) {
        g_rowptr[i] = run;
        g_cursor[i] = run;
        run += g_deg[i];
    }
    if (gtid == 0) g_rowptr[n] = g_total;
    grid_sync(PREP_BLOCKS);

    for (int i = gtid; i < e; i += T) {
        int pos = atomicAdd(&g_cursor[dst[i]], 1);
        g_esrc[pos] = src[i];
    }
}

// ---------------------------------------------------------------- weight prep
// Images for W2 (slot 2) and W3 (slot 3); slot 0 built by k_wcomb.
__global__ void k_wprep(const float* __restrict__ W2, const float* __restrict__ W3) {
    int gid = blockIdx.x * blockDim.x + threadIdx.x;   // 2 * 8192
    int L   = 2 + (gid >> 13);
    int idx = gid & 8191;
    if (L > 3) return;
    int N = (L == 3) ? 64 : 128;
    int nn = idx >> 6, m = idx & 63;
    if (nn >= N) return;
    const float* W = (L == 2) ? W2 : W3;
    float v0 = W[(size_t)(2 * m) * N + nn];
    float v1 = W[(size_t)(2 * m + 1) * N + nn];
    uint32_t lo, hi = packh2hl(v0, v1, lo);
    int w = widx(m);
    g_whi[L][nn * 64 + w] = hi;
    g_wlo[L][nn * 64 + w] = lo;
}

// ---------------------------------------------------------------- combined weight
// Wc = W_emb @ W1 (128x128, fp32), fp16 hi/lo into slot 0; bc = b_emb @ W1.
__global__ void k_wcomb(const float* __restrict__ We, const float* __restrict__ W1,
                        const float* __restrict__ be) {
    int gid = blockIdx.x * blockDim.x + threadIdx.x;   // 8192
    int m = gid >> 7, nn = gid & 127;
    if (m < 64) {
        float v0 = 0.f, v1 = 0.f;
        const float* r0 = &We[(size_t)(2 * m) * 128];
        const float* r1 = &We[(size_t)(2 * m + 1) * 128];
#pragma unroll 4
        for (int j = 0; j < 128; j++) {
            float w = W1[(size_t)j * 128 + nn];
            v0 = fmaf(r0[j], w, v0);
            v1 = fmaf(r1[j], w, v1);
        }
        uint32_t lo, hi = packh2hl(v0, v1, lo);
        int w = widx(m);
        g_whi[0][nn * 64 + w] = hi;
        g_wlo[0][nn * 64 + w] = lo;
    }
    if (blockIdx.x == 0 && threadIdx.x < 128) {
        int nc = threadIdx.x;
        float b = 0.f;
        for (int j = 0; j < 128; j++) b = fmaf(be[j], W1[(size_t)j * 128 + nc], b);
        g_bc[nc] = b;
    }
}

// ---------------------------------------------------------------- x convert
__global__ void k_xconv(const float* __restrict__ x, uint32_t* __restrict__ o16, int n) {
    int gid = blockIdx.x * blockDim.x + threadIdx.x;   // n * 64
    int node = gid >> 6, m = gid & 63;
    if (node >= n) return;
    float2 v = *reinterpret_cast<const float2*>(&x[(size_t)node * 128 + m * 2]);
    o16[(size_t)node * 64 + widx(m)] = packh2(v.x, v.y);
}

// ---------------------------------------------------------------- mma GEMM
// t16[M,BN] = fp16( (A[M,128] @ W[128,BN] + bias) * dis[row] )
// A: fp16 single plane (k-permuted). W: fp16 hi/lo. 2-term: A*Wh + A*Wl.
// 3-stage cp.async pipeline (prefetch distance 2).
template <int BN, bool SCALE, bool BIAS>
__global__ void __launch_bounds__(256, 2)
k_mgemm(const uint32_t* __restrict__ A16,
        const uint32_t* __restrict__ Whi, const uint32_t* __restrict__ Wlo,
        const float* __restrict__ bias, const float* __restrict__ dis,
        uint32_t* __restrict__ out16, int M)
{
    constexpr int NT = BN / 16;
    __shared__ __align__(16) uint32_t sA[3][128 * 8];
    __shared__ __align__(16) uint32_t sW[3][2][BN * 8];

    const int tid  = threadIdx.x;
    const int wid  = tid >> 5, lane = tid & 31;
    const int g    = lane >> 2, t = lane & 3;
    const int wm   = wid & 3, wn = wid >> 2;
    const int row0 = blockIdx.x * 128;

    const uint32_t sAb = sm32(sA);
    const uint32_t sWb = sm32(sW);
    constexpr uint32_t A_P = 128 * 8 * 4;
    constexpr uint32_t W_P = BN * 8 * 4;

    float acc[2][NT][4];
#pragma unroll
    for (int i = 0; i < 2; i++)
#pragma unroll
        for (int j = 0; j < NT; j++)
#pragma unroll
            for (int q = 0; q < 4; q++) acc[i][j][q] = 0.f;

    auto issue = [&](int kt, int buf) {
        int r = tid >> 1, h = tid & 1;
        int gr = row0 + r; if (gr >= M) gr = M - 1;
        uint32_t off = (uint32_t)(r * 8 + h * 4) * 4u;
        cpa16(sAb + (uint32_t)buf * A_P + off, A16 + (size_t)gr * 64 + kt * 8 + h * 4);
        if (tid < BN * 2) {
            uint32_t wbase = sWb + (uint32_t)buf * 2u * W_P;
            cpa16(wbase + off,       Whi + r * 64 + kt * 8 + h * 4);
            cpa16(wbase + W_P + off, Wlo + r * 64 + kt * 8 + h * 4);
        }
        asm volatile("cp.async.commit_group;" ::: "memory");
    };

    issue(0, 0);
    issue(1, 1);
    for (int kt = 0; kt < 8; kt++) {
        const int buf = kt % 3;
        if (kt < 6) {
            issue(kt + 2, (kt + 2) % 3);
            asm volatile("cp.async.wait_group 2;" ::: "memory");
        } else if (kt == 6) {
            asm volatile("cp.async.wait_group 1;" ::: "memory");
        } else {
            asm volatile("cp.async.wait_group 0;" ::: "memory");
        }
        __syncthreads();

        const uint32_t* pA  = sA[buf];
        const uint32_t* pWh = sW[buf][0];
        const uint32_t* pWl = sW[buf][1];

        uint32_t a[2][4];
#pragma unroll
        for (int mt = 0; mt < 2; mt++) {
            int r0 = wm * 32 + mt * 16 + g;
            uint2 v;
            v = *reinterpret_cast<const uint2*>(&pA[r0 * 8 + t * 2]);
            a[mt][0] = v.x; a[mt][2] = v.y;
            v = *reinterpret_cast<const uint2*>(&pA[(r0 + 8) * 8 + t * 2]);
            a[mt][1] = v.x; a[mt][3] = v.y;
        }
#pragma unroll
        for (int nt = 0; nt < NT; nt++) {
            int rn = wn * (NT * 8) + nt * 8 + g;
            uint2 bh = *reinterpret_cast<const uint2*>(&pWh[rn * 8 + t * 2]);
            uint2 bl = *reinterpret_cast<const uint2*>(&pWl[rn * 8 + t * 2]);
#pragma unroll
            for (int mt = 0; mt < 2; mt++) {
                MMA_F16(acc[mt][nt], a[mt], bh);
                MMA_F16(acc[mt][nt], a[mt], bl);
            }
        }
        __syncthreads();
    }

    // ---- epilogue: v = (acc + bias) * dis ----
#pragma unroll
    for (int mt = 0; mt < 2; mt++) {
        int r0 = row0 + wm * 32 + mt * 16 + g;
        int r1 = r0 + 8;
        bool ok0 = r0 < M, ok1 = r1 < M;
        float sc0 = (SCALE && ok0) ? dis[r0] : 1.0f;
        float sc1 = (SCALE && ok1) ? dis[r1] : 1.0f;
#pragma unroll
        for (int nt = 0; nt < NT; nt++) {
            int c = wn * (NT * 8) + nt * 8 + 2 * t;
            float b0 = 0.f, b1 = 0.f;
            if (BIAS) {
                float2 bb = *reinterpret_cast<const float2*>(&bias[c]);
                b0 = bb.x; b1 = bb.y;
            }
            float v00 = (acc[mt][nt][0] + b0) * sc0;
            float v01 = (acc[mt][nt][1] + b1) * sc0;
            float v10 = (acc[mt][nt][2] + b0) * sc1;
            float v11 = (acc[mt][nt][3] + b1) * sc1;
            if (ok0) out16[(size_t)r0 * (BN / 2) + (c >> 1)] = packh2(v00, v01);
            if (ok1) out16[(size_t)r1 * (BN / 2) + (c >> 1)] = packh2(v10, v11);
        }
    }
}

// ---------------------------------------------------------------- aggregation
// One warp per dst node; tb16 holds half2-packed GEMM output.
// COLS==128: emit fp16 single plane (k-permuted) for the next GEMM.
// COLS==64: fused pool via red.global.add.v2.f32.
template <int COLS, bool RELU>
__global__ void k_agg(const uint32_t* __restrict__ tb16, const int* __restrict__ rowptr,
                      const int* __restrict__ esrc, const float* __restrict__ dis,
                      const float* __restrict__ bias, uint32_t* __restrict__ o16,
                      const int* __restrict__ batch, float* __restrict__ dout, int n) {
    const int warp = (blockIdx.x * blockDim.x + threadIdx.x) >> 5;
    const int lane = threadIdx.x & 31;
    if (warp >= n) return;
    const int beg = __ldg(&rowptr[warp]);
    const int end = __ldg(&rowptr[warp + 1]);

    if constexpr (COLS == 128) {
        uint2 sv = *reinterpret_cast<const uint2*>(&tb16[(size_t)warp * 64 + lane * 2]);
        float2 a0 = unph2(sv.x), a1 = unph2(sv.y);
        float4 acc = make_float4(a0.x, a0.y, a1.x, a1.y);
        int e = beg;
        for (; e + 8 <= end; e += 8) {
            int s[8];
#pragma unroll
            for (int u = 0; u < 8; u++) s[u] = __ldg(&esrc[e + u]);
            uint2 v[8];
#pragma unroll
            for (int u = 0; u < 8; u++)
                v[u] = *reinterpret_cast<const uint2*>(&tb16[(size_t)s[u] * 64 + lane * 2]);
#pragma unroll
            for (int u = 0; u < 8; u++) {
                float2 f0 = unph2(v[u].x), f1 = unph2(v[u].y);
                acc.x += f0.x; acc.y += f0.y; acc.z += f1.x; acc.w += f1.y;
            }
        }
        for (; e < end; e++) {
            int s = __ldg(&esrc[e]);
            uint2 v = *reinterpret_cast<const uint2*>(&tb16[(size_t)s * 64 + lane * 2]);
            float2 f0 = unph2(v.x), f1 = unph2(v.y);
            acc.x += f0.x; acc.y += f0.y; acc.z += f1.x; acc.w += f1.y;
        }
        float d = dis[warp];
        float4 b = *reinterpret_cast<const float4*>(&bias[lane * 4]);
        float4 r;
        r.x = fmaf(acc.x, d, b.x);
        r.y = fmaf(acc.y, d, b.y);
        r.z = fmaf(acc.z, d, b.z);
        r.w = fmaf(acc.w, d, b.w);
        if (RELU) {
            r.x = fmaxf(r.x, 0.f); r.y = fmaxf(r.y, 0.f);
            r.z = fmaxf(r.z, 0.f); r.w = fmaxf(r.w, 0.f);
        }
        int m0 = lane * 2;
        o16[(size_t)warp * 64 + widx(m0)]     = packh2(r.x, r.y);
        o16[(size_t)warp * 64 + widx(m0 + 1)] = packh2(r.z, r.w);
    } else {  // COLS == 64: fused pool
        float2 acc = unph2(tb16[(size_t)warp * 32 + lane]);
        int e = beg;
        for (; e + 8 <= end; e += 8) {
            int s[8];
#pragma unroll
            for (int u = 0; u < 8; u++) s[u] = __ldg(&esrc[e + u]);
            uint32_t v[8];
#pragma unroll
            for (int u = 0; u < 8; u++) v[u] = tb16[(size_t)s[u] * 32 + lane];
#pragma unroll
            for (int u = 0; u < 8; u++) {
                float2 f = unph2(v[u]);
                acc.x += f.x; acc.y += f.y;
            }
        }
        for (; e < end; e++) {
            int s = __ldg(&esrc[e]);
            float2 f = unph2(tb16[(size_t)s * 32 + lane]);
            acc.x += f.x; acc.y += f.y;
        }
        float d = dis[warp];
        float2 b = *reinterpret_cast<const float2*>(&bias[lane * 2]);
        float rx = fmaf(acc.x, d, b.x);
        float ry = fmaf(acc.y, d, b.y);
        int gidx = __ldg(&batch[warp]);
        float* a = &dout[(size_t)gidx * 64 + lane * 2];
        asm volatile("red.global.add.v2.f32 [%0], {%1,%2};"
                     :: "l"(a), "f"(rx), "f"(ry) : "memory");
    }
}

// ---------------------------------------------------------------- launch
extern "C" void kernel_launch(void* const* d_in, const int* in_sizes, int n_in,
                              void* d_out, int out_size) {
    const float* x     = (const float*)d_in[0];
    const int*   ei    = (const int*)  d_in[1];
    const int*   batch = (const int*)  d_in[2];
    const float* W_emb = (const float*)d_in[3];
    const float* b_emb = (const float*)d_in[4];
    const float* W1    = (const float*)d_in[5];
    const float* b1    = (const float*)d_in[6];
    const float* W2    = (const float*)d_in[7];
    const float* b2    = (const float*)d_in[8];
    const float* W3    = (const float*)d_in[9];
    const float* b3    = (const float*)d_in[10];

    const int n = in_sizes[2];
    const int e = in_sizes[1] / 2;
    const int* src = ei;
    const int* dst = ei + e;

    float *dis, *bc;
    int *rowptr, *esrc;
    uint32_t *t16, *a16, *b16, *whi, *wlo;
    cudaGetSymbolAddress((void**)&dis,    g_dis);
    cudaGetSymbolAddress((void**)&bc,     g_bc);
    cudaGetSymbolAddress((void**)&rowptr, g_rowptr);
    cudaGetSymbolAddress((void**)&esrc,   g_esrc);
    cudaGetSymbolAddress((void**)&t16,    g_t16);
    cudaGetSymbolAddress((void**)&a16,    g_a16);
    cudaGetSymbolAddress((void**)&b16,    g_b16);
    cudaGetSymbolAddress((void**)&whi,    g_whi);
    cudaGetSymbolAddress((void**)&wlo,    g_wlo);

    auto cdiv = [](long long a, long long b) { return (int)((a + b - 1) / b); };

    // 0: W2/W3 images
    k_wprep<<<cdiv(2 * 8192, 256), 256>>>(W2, W3);
    // 1: combined Wc = W_emb@W1 image (slot 0) + bc = b_emb@W1
    k_wcomb<<<32, 256>>>(W_emb, W1, b_emb);
    // 2: x -> fp16
    k_xconv<<<cdiv((long long)n * 64, 256), 256>>>(x, a16, n);
    // 3: fused prep (CSR + dis + zero d_out)    (<- profiled slot)
    k_prep<<<PREP_BLOCKS, PREP_THREADS>>>(src, dst, e, n, (float*)d_out, out_size / 4);
    // 4: layer-1 GEMM (folded embedding)  t16 = fp16((x@Wc + bc) * dis)
    k_mgemm<128, true, true><<<cdiv(n, 128), 256>>>(
        a16, whi + 0 * 8192, wlo + 0 * 8192, bc, dis, t16, n);
    // 5: layer-1 agg -> fp16 (B set)
    k_agg<128, true><<<cdiv(n, 8), 256>>>(t16, rowptr, esrc, dis, b1, b16,
                                          nullptr, nullptr, n);
    // 6-7: layer 2
    k_mgemm<128, true, false><<<cdiv(n, 128), 256>>>(
        b16, whi + 2 * 8192, wlo + 2 * 8192, nullptr, dis, t16, n);
    k_agg<128, true><<<cdiv(n, 8), 256>>>(t16, rowptr, esrc, dis, b2, a16,
                                          nullptr, nullptr, n);
    // 8-9: layer 3 (BN = 64, no relu) + fused pool
    k_mgemm<64, true, false><<<cdiv(n, 128), 256>>>(
        a16, whi + 3 * 8192, wlo + 3 * 8192, nullptr, dis, t16, n);
    k_agg<64, false><<<cdiv(n, 8), 256>>>(t16, rowptr, esrc, dis, b3, nullptr,
                                          batch, (float*)d_out, n);
}

// round 12
// speedup vs baseline: 1.9723x; 1.0419x over previous
#include <cuda_runtime.h>
#include <cuda_fp16.h>
#include <cstdint>

#define NMAX  100000
#define EMAX  1600000
#define PREP_BLOCKS 256
#define PREP_THREADS 512

// ---------------------------------------------------------------- scratch
__device__ float    g_dis[NMAX];
__device__ int      g_deg [NMAX];
__device__ int      g_rowptr[NMAX + 1];
__device__ int      g_cursor[NMAX];
__device__ int      g_esrc[EMAX];
__device__ uint32_t g_t16[NMAX * 64];      // GEMM output as half2 pairs (agg input)
__device__ uint32_t g_a16[NMAX * 64];      // fp16 activations (A set, k-permuted)
__device__ uint32_t g_b16[NMAX * 64];      // fp16 activations (B set, k-permuted)
__device__ uint32_t g_whi[4][8192], g_wlo[4][8192];  // fp16 hi/lo W^T images
__device__ float    g_bc[128];             // b_emb @ W1
__device__ int      g_bsum[PREP_BLOCKS];
__device__ int      g_boff[PREP_BLOCKS];
__device__ int      g_total;
__device__ unsigned g_bar;

// ---------------------------------------------------------------- helpers
__device__ __forceinline__ uint32_t sm32(const void* p) {
    uint32_t a;
    asm("{ .reg .u64 t; cvta.to.shared.u64 t, %1; cvt.u32.u64 %0, t; }" : "=r"(a) : "l"(p));
    return a;
}
__device__ __forceinline__ void cpa16(uint32_t dst, const void* src) {
    asm volatile("cp.async.cg.shared.global [%0], [%1], 16;" :: "r"(dst), "l"(src));
}
__device__ __forceinline__ uint32_t packh2(float v0, float v1) {
    __half2 h = __floats2half2_rn(v0, v1);
    return *reinterpret_cast<uint32_t*>(&h);
}
__device__ __forceinline__ float2 unph2(uint32_t u) {
    return __half22float2(*reinterpret_cast<__half2*>(&u));
}
// fp16 hi/lo split of (v0, v1)
__device__ __forceinline__ uint32_t packh2hl(float v0, float v1, uint32_t& lo) {
    __half2 h = __floats2half2_rn(v0, v1);
    uint32_t hb = *reinterpret_cast<uint32_t*>(&h);
    float2 hf = __half22float2(h);
    __half2 l = __floats2half2_rn(v0 - hf.x, v1 - hf.y);
    lo = *reinterpret_cast<uint32_t*>(&l);
    return hb;
}
// k-pair permuted uint index within a 64-uint (128 half) row, m = k-pair index 0..63
__device__ __forceinline__ int widx(int m) {
    int mg = m & 7;
    return ((m >> 3) << 3) + ((mg & 3) << 1) + (mg >> 2);
}
#define MMA_F16(d, a, b) \
    asm volatile("mma.sync.aligned.m16n8k16.row.col.f32.f16.f16.f32 " \
        "{%0,%1,%2,%3}, {%4,%5,%6,%7}, {%8,%9}, {%0,%1,%2,%3};" \
        : "+f"((d)[0]), "+f"((d)[1]), "+f"((d)[2]), "+f"((d)[3]) \
        : "r"((a)[0]), "r"((a)[1]), "r"((a)[2]), "r"((a)[3]), "r"((b).x), "r"((b).y))

// ---------------------------------------------------------------- grid sync
__device__ __forceinline__ void grid_sync(int nb) {
    __syncthreads();
    if (threadIdx.x == 0) {
        __threadfence();
        unsigned ticket = atomicAdd(&g_bar, 1u);
        unsigned phase  = ticket / (unsigned)nb + 1u;
        while (atomicAdd(&g_bar, 0u) < phase * (unsigned)nb) { }
    }
    __syncthreads();
}

// ---------------------------------------------------------------- fused prep
// phase0: zero deg
// phase1: degree histogram (REDG) + xconv + W2/W3 images + Wc/bc + zero d_out
// phase2: dis + scan partials ... phase5: permute  (CSR build)
__global__ __launch_bounds__(PREP_THREADS, 1)
void k_prep(const int* __restrict__ src, const int* __restrict__ dst, int e, int n,
            float* __restrict__ d_out, int out4,
            const float* __restrict__ x, const float* __restrict__ We,
            const float* __restrict__ W1, const float* __restrict__ W2,
            const float* __restrict__ W3, const float* __restrict__ be,
            uint32_t* __restrict__ a16) {
    const int tid  = threadIdx.x;
    const int lane = tid & 31, wid = tid >> 5;
    const int T    = PREP_BLOCKS * PREP_THREADS;
    const int gtid = blockIdx.x * PREP_THREADS + tid;
    __shared__ int sh[32];
    __shared__ int s_boff;

    // ---- phase 0: zero degree counters ----
    for (int i = gtid; i < n; i += T) g_deg[i] = 0;
    grid_sync(PREP_BLOCKS);

    // ---- phase 1: histogram + independent prologue work ----
    for (int i = gtid; i < e; i += T) atomicAdd(&g_deg[dst[i]], 1);

    // xconv: x -> fp16 (k-permuted)
    for (int i = gtid; i < n * 64; i += T) {
        int node = i >> 6, m = i & 63;
        float2 v = *reinterpret_cast<const float2*>(&x[(size_t)node * 128 + m * 2]);
        a16[(size_t)node * 64 + widx(m)] = packh2(v.x, v.y);
    }
    // W2/W3 images
    for (int i = gtid; i < 2 * 8192; i += T) {
        int L = 2 + (i >> 13);
        int idx = i & 8191;
        int N = (L == 3) ? 64 : 128;
        int nn = idx >> 6, m = idx & 63;
        if (nn < N) {
            const float* W = (L == 2) ? W2 : W3;
            float v0 = W[(size_t)(2 * m) * N + nn];
            float v1 = W[(size_t)(2 * m + 1) * N + nn];
            uint32_t lo, hi = packh2hl(v0, v1, lo);
            int w = widx(m);
            g_whi[L][nn * 64 + w] = hi;
            g_wlo[L][nn * 64 + w] = lo;
        }
    }
    // Wc = W_emb @ W1 (slot 0) + bc = b_emb @ W1, spread 1-in-16 gids
    if ((gtid & 15) == 0) {
        int j = gtid >> 4;
        if (j < 8192) {
            int m = j >> 7, nn = j & 127;
            float v0 = 0.f, v1 = 0.f;
            const float* r0 = &We[(size_t)(2 * m) * 128];
            const float* r1 = &We[(size_t)(2 * m + 1) * 128];
#pragma unroll 4
            for (int k = 0; k < 128; k++) {
                float w = W1[(size_t)k * 128 + nn];
                v0 = fmaf(r0[k], w, v0);
                v1 = fmaf(r1[k], w, v1);
            }
            uint32_t lo, hi = packh2hl(v0, v1, lo);
            int w = widx(m);
            g_whi[0][nn * 64 + w] = hi;
            g_wlo[0][nn * 64 + w] = lo;
        }
        if (j < 128) {
            float b = 0.f;
            for (int k = 0; k < 128; k++) b = fmaf(be[k], W1[(size_t)k * 128 + j], b);
            g_bc[j] = b;
        }
    }
    // zero d_out
    float4* o4 = reinterpret_cast<float4*>(d_out);
    for (int i = gtid; i < out4; i += T) o4[i] = make_float4(0.f, 0.f, 0.f, 0.f);
    grid_sync(PREP_BLOCKS);

    // ---- phase 2: dis + per-thread chunk sums + block scan ----
    for (int i = gtid; i < n; i += T) g_dis[i] = rsqrtf((float)g_deg[i] + 1.0f);

    const int per = (n + T - 1) / T;
    const int cb  = gtid * per;
    const int ce  = min(cb + per, n);
    int csum = 0;
    for (int i = cb; i < ce; i++) csum += g_deg[i];

    if (tid < 32) sh[tid] = 0;
    __syncthreads();

    int x0 = csum;
#pragma unroll
    for (int o = 1; o < 32; o <<= 1) {
        int y = __shfl_up_sync(0xffffffffu, x0, o);
        if (lane >= o) x0 += y;
    }
    if (lane == 31) sh[wid] = x0;
    __syncthreads();
    if (wid == 0) {
        int w = sh[lane];
        int xx = w;
#pragma unroll
        for (int o = 1; o < 32; o <<= 1) {
            int y = __shfl_up_sync(0xffffffffu, xx, o);
            if (lane >= o) xx += y;
        }
        sh[lane] = xx - w;
        if (lane == 31) g_bsum[blockIdx.x] = xx;
    }
    __syncthreads();
    const int thr_excl = x0 - csum + sh[wid];
    grid_sync(PREP_BLOCKS);

    // ---- phase 3: block 0 scans the block totals ----
    if (blockIdx.x == 0 && wid == 0) {
        int carry = 0;
        for (int base = 0; base < PREP_BLOCKS; base += 32) {
            int v = g_bsum[base + lane];
            int s = v;
#pragma unroll
            for (int o = 1; o < 32; o <<= 1) {
                int y = __shfl_up_sync(0xffffffffu, s, o);
                if (lane >= o) s += y;
            }
            g_boff[base + lane] = s - v + carry;
            carry += __shfl_sync(0xffffffffu, s, 31);
        }
        if (lane == 0) g_total = carry;
    }
    grid_sync(PREP_BLOCKS);

    // ---- phase 4: rowptr / cursor ----
    if (tid == 0) s_boff = g_boff[blockIdx.x];
    __syncthreads();
    int run = s_boff + thr_excl;
    for (int i = cb; i < ce; i++) {
        g_rowptr[i] = run;
        g_cursor[i] = run;
        run += g_deg[i];
    }
    if (gtid == 0) g_rowptr[n] = g_total;
    grid_sync(PREP_BLOCKS);

    // ---- phase 5: permute edges into CSR order ----
    for (int i = gtid; i < e; i += T) {
        int pos = atomicAdd(&g_cursor[dst[i]], 1);
        g_esrc[pos] = src[i];
    }
}

// ---------------------------------------------------------------- mma GEMM
// t16[M,BN] = fp16( (A[M,128] @ W[128,BN] + bias) * dis[row] )
// A: fp16 single plane (k-permuted). W: fp16 hi/lo. 2-term: A*Wh + A*Wl.
// 3-stage cp.async pipeline (prefetch distance 2).
template <int BN, bool SCALE, bool BIAS>
__global__ void __launch_bounds__(256, 2)
k_mgemm(const uint32_t* __restrict__ A16,
        const uint32_t* __restrict__ Whi, const uint32_t* __restrict__ Wlo,
        const float* __restrict__ bias, const float* __restrict__ dis,
        uint32_t* __restrict__ out16, int M)
{
    constexpr int NT = BN / 16;
    __shared__ __align__(16) uint32_t sA[3][128 * 8];
    __shared__ __align__(16) uint32_t sW[3][2][BN * 8];

    const int tid  = threadIdx.x;
    const int wid  = tid >> 5, lane = tid & 31;
    const int g    = lane >> 2, t = lane & 3;
    const int wm   = wid & 3, wn = wid >> 2;
    const int row0 = blockIdx.x * 128;

    const uint32_t sAb = sm32(sA);
    const uint32_t sWb = sm32(sW);
    constexpr uint32_t A_P = 128 * 8 * 4;
    constexpr uint32_t W_P = BN * 8 * 4;

    float acc[2][NT][4];
#pragma unroll
    for (int i = 0; i < 2; i++)
#pragma unroll
        for (int j = 0; j < NT; j++)
#pragma unroll
            for (int q = 0; q < 4; q++) acc[i][j][q] = 0.f;

    auto issue = [&](int kt, int buf) {
        int r = tid >> 1, h = tid & 1;
        int gr = row0 + r; if (gr >= M) gr = M - 1;
        uint32_t off = (uint32_t)(r * 8 + h * 4) * 4u;
        cpa16(sAb + (uint32_t)buf * A_P + off, A16 + (size_t)gr * 64 + kt * 8 + h * 4);
        if (tid < BN * 2) {
            uint32_t wbase = sWb + (uint32_t)buf * 2u * W_P;
            cpa16(wbase + off,       Whi + r * 64 + kt * 8 + h * 4);
            cpa16(wbase + W_P + off, Wlo + r * 64 + kt * 8 + h * 4);
        }
        asm volatile("cp.async.commit_group;" ::: "memory");
    };

    issue(0, 0);
    issue(1, 1);
    for (int kt = 0; kt < 8; kt++) {
        const int buf = kt % 3;
        if (kt < 6) {
            issue(kt + 2, (kt + 2) % 3);
            asm volatile("cp.async.wait_group 2;" ::: "memory");
        } else if (kt == 6) {
            asm volatile("cp.async.wait_group 1;" ::: "memory");
        } else {
            asm volatile("cp.async.wait_group 0;" ::: "memory");
        }
        __syncthreads();

        const uint32_t* pA  = sA[buf];
        const uint32_t* pWh = sW[buf][0];
        const uint32_t* pWl = sW[buf][1];

        uint32_t a[2][4];
#pragma unroll
        for (int mt = 0; mt < 2; mt++) {
            int r0 = wm * 32 + mt * 16 + g;
            uint2 v;
            v = *reinterpret_cast<const uint2*>(&pA[r0 * 8 + t * 2]);
            a[mt][0] = v.x; a[mt][2] = v.y;
            v = *reinterpret_cast<const uint2*>(&pA[(r0 + 8) * 8 + t * 2]);
            a[mt][1] = v.x; a[mt][3] = v.y;
        }
#pragma unroll
        for (int nt = 0; nt < NT; nt++) {
            int rn = wn * (NT * 8) + nt * 8 + g;
            uint2 bh = *reinterpret_cast<const uint2*>(&pWh[rn * 8 + t * 2]);
            uint2 bl = *reinterpret_cast<const uint2*>(&pWl[rn * 8 + t * 2]);
#pragma unroll
            for (int mt = 0; mt < 2; mt++) {
                MMA_F16(acc[mt][nt], a[mt], bh);
                MMA_F16(acc[mt][nt], a[mt], bl);
            }
        }
        __syncthreads();
    }

    // ---- epilogue: v = (acc + bias) * dis ----
#pragma unroll
    for (int mt = 0; mt < 2; mt++) {
        int r0 = row0 + wm * 32 + mt * 16 + g;
        int r1 = r0 + 8;
        bool ok0 = r0 < M, ok1 = r1 < M;
        float sc0 = (SCALE && ok0) ? dis[r0] : 1.0f;
        float sc1 = (SCALE && ok1) ? dis[r1] : 1.0f;
#pragma unroll
        for (int nt = 0; nt < NT; nt++) {
            int c = wn * (NT * 8) + nt * 8 + 2 * t;
            float b0 = 0.f, b1 = 0.f;
            if (BIAS) {
                float2 bb = *reinterpret_cast<const float2*>(&bias[c]);
                b0 = bb.x; b1 = bb.y;
            }
            float v00 = (acc[mt][nt][0] + b0) * sc0;
            float v01 = (acc[mt][nt][1] + b1) * sc0;
            float v10 = (acc[mt][nt][2] + b0) * sc1;
            float v11 = (acc[mt][nt][3] + b1) * sc1;
            if (ok0) out16[(size_t)r0 * (BN / 2) + (c >> 1)] = packh2(v00, v01);
            if (ok1) out16[(size_t)r1 * (BN / 2) + (c >> 1)] = packh2(v10, v11);
        }
    }
}

// ---------------------------------------------------------------- aggregation
// One warp per dst node; tb16 holds half2-packed GEMM output.
// COLS==128: emit fp16 single plane (k-permuted) for the next GEMM.
// COLS==64: fused pool via red.global.add.v2.f32.
template <int COLS, bool RELU>
__global__ void k_agg(const uint32_t* __restrict__ tb16, const int* __restrict__ rowptr,
                      const int* __restrict__ esrc, const float* __restrict__ dis,
                      const float* __restrict__ bias, uint32_t* __restrict__ o16,
                      const int* __restrict__ batch, float* __restrict__ dout, int n) {
    const int warp = (blockIdx.x * blockDim.x + threadIdx.x) >> 5;
    const int lane = threadIdx.x & 31;
    if (warp >= n) return;
    const int beg = __ldg(&rowptr[warp]);
    const int end = __ldg(&rowptr[warp + 1]);

    if constexpr (COLS == 128) {
        uint2 sv = *reinterpret_cast<const uint2*>(&tb16[(size_t)warp * 64 + lane * 2]);
        float2 a0 = unph2(sv.x), a1 = unph2(sv.y);
        float4 acc = make_float4(a0.x, a0.y, a1.x, a1.y);
        int e = beg;
        for (; e + 8 <= end; e += 8) {
            int s[8];
#pragma unroll
            for (int u = 0; u < 8; u++) s[u] = __ldg(&esrc[e + u]);
            uint2 v[8];
#pragma unroll
            for (int u = 0; u < 8; u++)
                v[u] = *reinterpret_cast<const uint2*>(&tb16[(size_t)s[u] * 64 + lane * 2]);
#pragma unroll
            for (int u = 0; u < 8; u++) {
                float2 f0 = unph2(v[u].x), f1 = unph2(v[u].y);
                acc.x += f0.x; acc.y += f0.y; acc.z += f1.x; acc.w += f1.y;
            }
        }
        for (; e < end; e++) {
            int s = __ldg(&esrc[e]);
            uint2 v = *reinterpret_cast<const uint2*>(&tb16[(size_t)s * 64 + lane * 2]);
            float2 f0 = unph2(v.x), f1 = unph2(v.y);
            acc.x += f0.x; acc.y += f0.y; acc.z += f1.x; acc.w += f1.y;
        }
        float d = dis[warp];
        float4 b = *reinterpret_cast<const float4*>(&bias[lane * 4]);
        float4 r;
        r.x = fmaf(acc.x, d, b.x);
        r.y = fmaf(acc.y, d, b.y);
        r.z = fmaf(acc.z, d, b.z);
        r.w = fmaf(acc.w, d, b.w);
        if (RELU) {
            r.x = fmaxf(r.x, 0.f); r.y = fmaxf(r.y, 0.f);
            r.z = fmaxf(r.z, 0.f); r.w = fmaxf(r.w, 0.f);
        }
        int m0 = lane * 2;
        o16[(size_t)warp * 64 + widx(m0)]     = packh2(r.x, r.y);
        o16[(size_t)warp * 64 + widx(m0 + 1)] = packh2(r.z, r.w);
    } else {  // COLS == 64: fused pool
        float2 acc = unph2(tb16[(size_t)warp * 32 + lane]);
        int e = beg;
        for (; e + 8 <= end; e += 8) {
            int s[8];
#pragma unroll
            for (int u = 0; u < 8; u++) s[u] = __ldg(&esrc[e + u]);
            uint32_t v[8];
#pragma unroll
            for (int u = 0; u < 8; u++) v[u] = tb16[(size_t)s[u] * 32 + lane];
#pragma unroll
            for (int u = 0; u < 8; u++) {
                float2 f = unph2(v[u]);
                acc.x += f.x; acc.y += f.y;
            }
        }
        for (; e < end; e++) {
            int s = __ldg(&esrc[e]);
            float2 f = unph2(tb16[(size_t)s * 32 + lane]);
            acc.x += f.x; acc.y += f.y;
        }
        float d = dis[warp];
        float2 b = *reinterpret_cast<const float2*>(&bias[lane * 2]);
        float rx = fmaf(acc.x, d, b.x);
        float ry = fmaf(acc.y, d, b.y);
        int gidx = __ldg(&batch[warp]);
        float* a = &dout[(size_t)gidx * 64 + lane * 2];
        asm volatile("red.global.add.v2.f32 [%0], {%1,%2};"
                     :: "l"(a), "f"(rx), "f"(ry) : "memory");
    }
}

// ---------------------------------------------------------------- launch
extern "C" void kernel_launch(void* const* d_in, const int* in_sizes, int n_in,
                              void* d_out, int out_size) {
    const float* x     = (const float*)d_in[0];
    const int*   ei    = (const int*)  d_in[1];
    const int*   batch = (const int*)  d_in[2];
    const float* W_emb = (const float*)d_in[3];
    const float* b_emb = (const float*)d_in[4];
    const float* W1    = (const float*)d_in[5];
    const float* b1    = (const float*)d_in[6];
    const float* W2    = (const float*)d_in[7];
    const float* b2    = (const float*)d_in[8];
    const float* W3    = (const float*)d_in[9];
    const float* b3    = (const float*)d_in[10];

    const int n = in_sizes[2];
    const int e = in_sizes[1] / 2;
    const int* src = ei;
    const int* dst = ei + e;

    float *dis, *bc;
    int *rowptr, *esrc;
    uint32_t *t16, *a16, *b16, *whi, *wlo;
    cudaGetSymbolAddress((void**)&dis,    g_dis);
    cudaGetSymbolAddress((void**)&bc,     g_bc);
    cudaGetSymbolAddress((void**)&rowptr, g_rowptr);
    cudaGetSymbolAddress((void**)&esrc,   g_esrc);
    cudaGetSymbolAddress((void**)&t16,    g_t16);
    cudaGetSymbolAddress((void**)&a16,    g_a16);
    cudaGetSymbolAddress((void**)&b16,    g_b16);
    cudaGetSymbolAddress((void**)&whi,    g_whi);
    cudaGetSymbolAddress((void**)&wlo,    g_wlo);

    auto cdiv = [](long long a, long long b) { return (int)((a + b - 1) / b); };

    // 0: fused prep (CSR + dis + weight images + Wc/bc + xconv + zero d_out)
    k_prep<<<PREP_BLOCKS, PREP_THREADS>>>(src, dst, e, n, (float*)d_out, out_size / 4,
                                          x, W_emb, W1, W2, W3, b_emb, a16);
    // 1: layer-1 GEMM (folded embedding)  t16 = fp16((x@Wc + bc) * dis)
    k_mgemm<128, true, true><<<cdiv(n, 128), 256>>>(
        a16, whi + 0 * 8192, wlo + 0 * 8192, bc, dis, t16, n);
    // 2: layer-1 agg -> fp16 (B set)
    k_agg<128, true><<<cdiv(n, 8), 256>>>(t16, rowptr, esrc, dis, b1, b16,
                                          nullptr, nullptr, n);
    // 3: layer-2 GEMM   (<- profiled slot)
    k_mgemm<128, true, false><<<cdiv(n, 128), 256>>>(
        b16, whi + 2 * 8192, wlo + 2 * 8192, nullptr, dis, t16, n);
    // 4: layer-2 agg
    k_agg<128, true><<<cdiv(n, 8), 256>>>(t16, rowptr, esrc, dis, b2, a16,
                                          nullptr, nullptr, n);
    // 5: layer-3 GEMM (BN = 64)
    k_mgemm<64, true, false><<<cdiv(n, 128), 256>>>(
        a16, whi + 3 * 8192, wlo + 3 * 8192, nullptr, dis, t16, n);
    // 6: layer-3 agg + fused pool
    k_agg<64, false><<<cdiv(n, 8), 256>>>(t16, rowptr, esrc, dis, b3, nullptr,
                                          batch, (float*)d_out, n);
}

// round 13
// speedup vs baseline: 2.1541x; 1.0922x over previous
#include <cuda_runtime.h>
#include <cuda_fp16.h>
#include <cstdint>

#define NMAX  100000
#define EMAX  1600000
#define PREP_BLOCKS 256
#define PREP_THREADS 512

// ---------------------------------------------------------------- scratch
__device__ float    g_dis[NMAX];
__device__ int      g_deg [NMAX];
__device__ int      g_rowptr[NMAX + 1];
__device__ int      g_cursor[NMAX];
__device__ int      g_esrc[EMAX];
__device__ uint32_t g_t16[NMAX * 64];      // GEMM output as half2 pairs (agg input)
__device__ uint32_t g_a16[NMAX * 64];      // fp16 activations (A set, k-permuted)
__device__ uint32_t g_b16[NMAX * 64];      // fp16 activations (B set, k-permuted)
__device__ uint32_t g_w16[4][8192];        // fp16 W^T images (single plane)
__device__ float    g_bc[128];             // b_emb @ W1
__device__ int      g_bsum[PREP_BLOCKS];
__device__ int      g_boff[PREP_BLOCKS];
__device__ int      g_total;
__device__ unsigned g_bar;

// ---------------------------------------------------------------- helpers
__device__ __forceinline__ uint32_t sm32(const void* p) {
    uint32_t a;
    asm("{ .reg .u64 t; cvta.to.shared.u64 t, %1; cvt.u32.u64 %0, t; }" : "=r"(a) : "l"(p));
    return a;
}
__device__ __forceinline__ void cpa16(uint32_t dst, const void* src) {
    asm volatile("cp.async.cg.shared.global [%0], [%1], 16;" :: "r"(dst), "l"(src));
}
__device__ __forceinline__ uint32_t packh2(float v0, float v1) {
    __half2 h = __floats2half2_rn(v0, v1);
    return *reinterpret_cast<uint32_t*>(&h);
}
__device__ __forceinline__ float2 unph2(uint32_t u) {
    return __half22float2(*reinterpret_cast<__half2*>(&u));
}
// k-pair permuted uint index within a 64-uint (128 half) row, m = k-pair index 0..63
__device__ __forceinline__ int widx(int m) {
    int mg = m & 7;
    return ((m >> 3) << 3) + ((mg & 3) << 1) + (mg >> 2);
}
#define MMA_F16(d, a, b) \
    asm volatile("mma.sync.aligned.m16n8k16.row.col.f32.f16.f16.f32 " \
        "{%0,%1,%2,%3}, {%4,%5,%6,%7}, {%8,%9}, {%0,%1,%2,%3};" \
        : "+f"((d)[0]), "+f"((d)[1]), "+f"((d)[2]), "+f"((d)[3]) \
        : "r"((a)[0]), "r"((a)[1]), "r"((a)[2]), "r"((a)[3]), "r"((b).x), "r"((b).y))

// ---------------------------------------------------------------- grid sync
__device__ __forceinline__ void grid_sync(int nb) {
    __syncthreads();
    if (threadIdx.x == 0) {
        __threadfence();
        unsigned ticket = atomicAdd(&g_bar, 1u);
        unsigned phase  = ticket / (unsigned)nb + 1u;
        while (atomicAdd(&g_bar, 0u) < phase * (unsigned)nb) { }
    }
    __syncthreads();
}

// ---------------------------------------------------------------- fused prep
__global__ __launch_bounds__(PREP_THREADS, 1)
void k_prep(const int* __restrict__ src, const int* __restrict__ dst, int e, int n,
            float* __restrict__ d_out, int out4,
            const float* __restrict__ x, const float* __restrict__ We,
            const float* __restrict__ W1, const float* __restrict__ W2,
            const float* __restrict__ W3, const float* __restrict__ be,
            uint32_t* __restrict__ a16) {
    const int tid  = threadIdx.x;
    const int lane = tid & 31, wid = tid >> 5;
    const int T    = PREP_BLOCKS * PREP_THREADS;
    const int gtid = blockIdx.x * PREP_THREADS + tid;
    __shared__ int sh[32];
    __shared__ int s_boff;

    // ---- phase 0: zero degree counters ----
    for (int i = gtid; i < n; i += T) g_deg[i] = 0;
    grid_sync(PREP_BLOCKS);

    // ---- phase 1: histogram + independent prologue work ----
    for (int i = gtid; i < e; i += T) atomicAdd(&g_deg[dst[i]], 1);

    // xconv: x -> fp16 (k-permuted)
    for (int i = gtid; i < n * 64; i += T) {
        int node = i >> 6, m = i & 63;
        float2 v = *reinterpret_cast<const float2*>(&x[(size_t)node * 128 + m * 2]);
        a16[(size_t)node * 64 + widx(m)] = packh2(v.x, v.y);
    }
    // W2/W3 images
    for (int i = gtid; i < 2 * 8192; i += T) {
        int L = 2 + (i >> 13);
        int idx = i & 8191;
        int N = (L == 3) ? 64 : 128;
        int nn = idx >> 6, m = idx & 63;
        if (nn < N) {
            const float* W = (L == 2) ? W2 : W3;
            float v0 = W[(size_t)(2 * m) * N + nn];
            float v1 = W[(size_t)(2 * m + 1) * N + nn];
            g_w16[L][nn * 64 + widx(m)] = packh2(v0, v1);
        }
    }
    // Wc = W_emb @ W1 (slot 0) + bc = b_emb @ W1, spread 1-in-16 gids
    if ((gtid & 15) == 0) {
        int j = gtid >> 4;
        if (j < 8192) {
            int m = j >> 7, nn = j & 127;
            float v0 = 0.f, v1 = 0.f;
            const float* r0 = &We[(size_t)(2 * m) * 128];
            const float* r1 = &We[(size_t)(2 * m + 1) * 128];
#pragma unroll 4
            for (int k = 0; k < 128; k++) {
                float w = W1[(size_t)k * 128 + nn];
                v0 = fmaf(r0[k], w, v0);
                v1 = fmaf(r1[k], w, v1);
            }
            g_w16[0][nn * 64 + widx(m)] = packh2(v0, v1);
        }
        if (j < 128) {
            float b = 0.f;
            for (int k = 0; k < 128; k++) b = fmaf(be[k], W1[(size_t)k * 128 + j], b);
            g_bc[j] = b;
        }
    }
    // zero d_out
    float4* o4 = reinterpret_cast<float4*>(d_out);
    for (int i = gtid; i < out4; i += T) o4[i] = make_float4(0.f, 0.f, 0.f, 0.f);
    grid_sync(PREP_BLOCKS);

    // ---- phase 2: dis + per-thread chunk sums + block scan ----
    for (int i = gtid; i < n; i += T) g_dis[i] = rsqrtf((float)g_deg[i] + 1.0f);

    const int per = (n + T - 1) / T;
    const int cb  = gtid * per;
    const int ce  = min(cb + per, n);
    int csum = 0;
    for (int i = cb; i < ce; i++) csum += g_deg[i];

    if (tid < 32) sh[tid] = 0;
    __syncthreads();

    int x0 = csum;
#pragma unroll
    for (int o = 1; o < 32; o <<= 1) {
        int y = __shfl_up_sync(0xffffffffu, x0, o);
        if (lane >= o) x0 += y;
    }
    if (lane == 31) sh[wid] = x0;
    __syncthreads();
    if (wid == 0) {
        int w = sh[lane];
        int xx = w;
#pragma unroll
        for (int o = 1; o < 32; o <<= 1) {
            int y = __shfl_up_sync(0xffffffffu, xx, o);
            if (lane >= o) xx += y;
        }
        sh[lane] = xx - w;
        if (lane == 31) g_bsum[blockIdx.x] = xx;
    }
    __syncthreads();
    const int thr_excl = x0 - csum + sh[wid];
    grid_sync(PREP_BLOCKS);

    // ---- phase 3: block 0 scans the block totals ----
    if (blockIdx.x == 0 && wid == 0) {
        int carry = 0;
        for (int base = 0; base < PREP_BLOCKS; base += 32) {
            int v = g_bsum[base + lane];
            int s = v;
#pragma unroll
            for (int o = 1; o < 32; o <<= 1) {
                int y = __shfl_up_sync(0xffffffffu, s, o);
                if (lane >= o) s += y;
            }
            g_boff[base + lane] = s - v + carry;
            carry += __shfl_sync(0xffffffffu, s, 31);
        }
        if (lane == 0) g_total = carry;
    }
    grid_sync(PREP_BLOCKS);

    // ---- phase 4: rowptr / cursor ----
    if (tid == 0) s_boff = g_boff[blockIdx.x];
    __syncthreads();
    int run = s_boff + thr_excl;
    for (int i = cb; i < ce; i++) {
        g_rowptr[i] = run;
        g_cursor[i] = run;
        run += g_deg[i];
    }
    if (gtid == 0) g_rowptr[n] = g_total;
    grid_sync(PREP_BLOCKS);

    // ---- phase 5: permute edges into CSR order ----
    for (int i = gtid; i < e; i += T) {
        int pos = atomicAdd(&g_cursor[dst[i]], 1);
        g_esrc[pos] = src[i];
    }
}

// ---------------------------------------------------------------- mma GEMM
// t16[M,BN] = fp16( (A[M,128] @ W[128,BN] + bias) * dis[row] )
// A and W both fp16 single plane (k-permuted). 3-stage cp.async pipeline.
template <int BN, bool SCALE, bool BIAS>
__global__ void __launch_bounds__(256, 2)
k_mgemm(const uint32_t* __restrict__ A16, const uint32_t* __restrict__ W16,
        const float* __restrict__ bias, const float* __restrict__ dis,
        uint32_t* __restrict__ out16, int M)
{
    constexpr int NT = BN / 16;
    __shared__ __align__(16) uint32_t sA[3][128 * 8];
    __shared__ __align__(16) uint32_t sW[3][BN * 8];

    const int tid  = threadIdx.x;
    const int wid  = tid >> 5, lane = tid & 31;
    const int g    = lane >> 2, t = lane & 3;
    const int wm   = wid & 3, wn = wid >> 2;
    const int row0 = blockIdx.x * 128;

    const uint32_t sAb = sm32(sA);
    const uint32_t sWb = sm32(sW);
    constexpr uint32_t A_P = 128 * 8 * 4;
    constexpr uint32_t W_P = BN * 8 * 4;

    float acc[2][NT][4];
#pragma unroll
    for (int i = 0; i < 2; i++)
#pragma unroll
        for (int j = 0; j < NT; j++)
#pragma unroll
            for (int q = 0; q < 4; q++) acc[i][j][q] = 0.f;

    auto issue = [&](int kt, int buf) {
        int r = tid >> 1, h = tid & 1;
        int gr = row0 + r; if (gr >= M) gr = M - 1;
        uint32_t off = (uint32_t)(r * 8 + h * 4) * 4u;
        cpa16(sAb + (uint32_t)buf * A_P + off, A16 + (size_t)gr * 64 + kt * 8 + h * 4);
        if (tid < BN * 2) {
            cpa16(sWb + (uint32_t)buf * W_P + off, W16 + r * 64 + kt * 8 + h * 4);
        }
        asm volatile("cp.async.commit_group;" ::: "memory");
    };

    issue(0, 0);
    issue(1, 1);
    for (int kt = 0; kt < 8; kt++) {
        const int buf = kt % 3;
        if (kt < 6) {
            issue(kt + 2, (kt + 2) % 3);
            asm volatile("cp.async.wait_group 2;" ::: "memory");
        } else if (kt == 6) {
            asm volatile("cp.async.wait_group 1;" ::: "memory");
        } else {
            asm volatile("cp.async.wait_group 0;" ::: "memory");
        }
        __syncthreads();

        const uint32_t* pA = sA[buf];
        const uint32_t* pW = sW[buf];

        uint32_t a[2][4];
#pragma unroll
        for (int mt = 0; mt < 2; mt++) {
            int r0 = wm * 32 + mt * 16 + g;
            uint2 v;
            v = *reinterpret_cast<const uint2*>(&pA[r0 * 8 + t * 2]);
            a[mt][0] = v.x; a[mt][2] = v.y;
            v = *reinterpret_cast<const uint2*>(&pA[(r0 + 8) * 8 + t * 2]);
            a[mt][1] = v.x; a[mt][3] = v.y;
        }
#pragma unroll
        for (int nt = 0; nt < NT; nt++) {
            int rn = wn * (NT * 8) + nt * 8 + g;
            uint2 bw = *reinterpret_cast<const uint2*>(&pW[rn * 8 + t * 2]);
#pragma unroll
            for (int mt = 0; mt < 2; mt++) {
                MMA_F16(acc[mt][nt], a[mt], bw);
            }
        }
        __syncthreads();
    }

    // ---- epilogue: v = (acc + bias) * dis ----
#pragma unroll
    for (int mt = 0; mt < 2; mt++) {
        int r0 = row0 + wm * 32 + mt * 16 + g;
        int r1 = r0 + 8;
        bool ok0 = r0 < M, ok1 = r1 < M;
        float sc0 = (SCALE && ok0) ? dis[r0] : 1.0f;
        float sc1 = (SCALE && ok1) ? dis[r1] : 1.0f;
#pragma unroll
        for (int nt = 0; nt < NT; nt++) {
            int c = wn * (NT * 8) + nt * 8 + 2 * t;
            float b0 = 0.f, b1 = 0.f;
            if (BIAS) {
                float2 bb = *reinterpret_cast<const float2*>(&bias[c]);
                b0 = bb.x; b1 = bb.y;
            }
            float v00 = (acc[mt][nt][0] + b0) * sc0;
            float v01 = (acc[mt][nt][1] + b1) * sc0;
            float v10 = (acc[mt][nt][2] + b0) * sc1;
            float v11 = (acc[mt][nt][3] + b1) * sc1;
            if (ok0) out16[(size_t)r0 * (BN / 2) + (c >> 1)] = packh2(v00, v01);
            if (ok1) out16[(size_t)r1 * (BN / 2) + (c >> 1)] = packh2(v10, v11);
        }
    }
}

// ---------------------------------------------------------------- aggregation
template <int COLS, bool RELU>
__global__ void k_agg(const uint32_t* __restrict__ tb16, const int* __restrict__ rowptr,
                      const int* __restrict__ esrc, const float* __restrict__ dis,
                      const float* __restrict__ bias, uint32_t* __restrict__ o16,
                      const int* __restrict__ batch, float* __restrict__ dout, int n) {
    const int warp = (blockIdx.x * blockDim.x + threadIdx.x) >> 5;
    const int lane = threadIdx.x & 31;
    if (warp >= n) return;
    const int beg = __ldg(&rowptr[warp]);
    const int end = __ldg(&rowptr[warp + 1]);

    if constexpr (COLS == 128) {
        uint2 sv = *reinterpret_cast<const uint2*>(&tb16[(size_t)warp * 64 + lane * 2]);
        float2 a0 = unph2(sv.x), a1 = unph2(sv.y);
        float4 acc = make_float4(a0.x, a0.y, a1.x, a1.y);
        int e = beg;
        for (; e + 8 <= end; e += 8) {
            int s[8];
#pragma unroll
            for (int u = 0; u < 8; u++) s[u] = __ldg(&esrc[e + u]);
            uint2 v[8];
#pragma unroll
            for (int u = 0; u < 8; u++)
                v[u] = *reinterpret_cast<const uint2*>(&tb16[(size_t)s[u] * 64 + lane * 2]);
#pragma unroll
            for (int u = 0; u < 8; u++) {
                float2 f0 = unph2(v[u].x), f1 = unph2(v[u].y);
                acc.x += f0.x; acc.y += f0.y; acc.z += f1.x; acc.w += f1.y;
            }
        }
        for (; e < end; e++) {
            int s = __ldg(&esrc[e]);
            uint2 v = *reinterpret_cast<const uint2*>(&tb16[(size_t)s * 64 + lane * 2]);
            float2 f0 = unph2(v.x), f1 = unph2(v.y);
            acc.x += f0.x; acc.y += f0.y; acc.z += f1.x; acc.w += f1.y;
        }
        float d = dis[warp];
        float4 b = *reinterpret_cast<const float4*>(&bias[lane * 4]);
        float4 r;
        r.x = fmaf(acc.x, d, b.x);
        r.y = fmaf(acc.y, d, b.y);
        r.z = fmaf(acc.z, d, b.z);
        r.w = fmaf(acc.w, d, b.w);
        if (RELU) {
            r.x = fmaxf(r.x, 0.f); r.y = fmaxf(r.y, 0.f);
            r.z = fmaxf(r.z, 0.f); r.w = fmaxf(r.w, 0.f);
        }
        int m0 = lane * 2;
        o16[(size_t)warp * 64 + widx(m0)]     = packh2(r.x, r.y);
        o16[(size_t)warp * 64 + widx(m0 + 1)] = packh2(r.z, r.w);
    } else {  // COLS == 64: fused pool
        float2 acc = unph2(tb16[(size_t)warp * 32 + lane]);
        int e = beg;
        for (; e + 8 <= end; e += 8) {
            int s[8];
#pragma unroll
            for (int u = 0; u < 8; u++) s[u] = __ldg(&esrc[e + u]);
            uint32_t v[8];
#pragma unroll
            for (int u = 0; u < 8; u++) v[u] = tb16[(size_t)s[u] * 32 + lane];
#pragma unroll
            for (int u = 0; u < 8; u++) {
                float2 f = unph2(v[u]);
                acc.x += f.x; acc.y += f.y;
            }
        }
        for (; e < end; e++) {
            int s = __ldg(&esrc[e]);
            float2 f = unph2(tb16[(size_t)s * 32 + lane]);
            acc.x += f.x; acc.y += f.y;
        }
        float d = dis[warp];
        float2 b = *reinterpret_cast<const float2*>(&bias[lane * 2]);
        float rx = fmaf(acc.x, d, b.x);
        float ry = fmaf(acc.y, d, b.y);
        int gidx = __ldg(&batch[warp]);
        float* a = &dout[(size_t)gidx * 64 + lane * 2];
        asm volatile("red.global.add.v2.f32 [%0], {%1,%2};"
                     :: "l"(a), "f"(rx), "f"(ry) : "memory");
    }
}

// ---------------------------------------------------------------- launch
extern "C" void kernel_launch(void* const* d_in, const int* in_sizes, int n_in,
                              void* d_out, int out_size) {
    const float* x     = (const float*)d_in[0];
    const int*   ei    = (const int*)  d_in[1];
    const int*   batch = (const int*)  d_in[2];
    const float* W_emb = (const float*)d_in[3];
    const float* b_emb = (const float*)d_in[4];
    const float* W1    = (const float*)d_in[5];
    const float* b1    = (const float*)d_in[6];
    const float* W2    = (const float*)d_in[7];
    const float* b2    = (const float*)d_in[8];
    const float* W3    = (const float*)d_in[9];
    const float* b3    = (const float*)d_in[10];

    const int n = in_sizes[2];
    const int e = in_sizes[1] / 2;
    const int* src = ei;
    const int* dst = ei + e;

    float *dis, *bc;
    int *rowptr, *esrc;
    uint32_t *t16, *a16, *b16, *w16;
    cudaGetSymbolAddress((void**)&dis,    g_dis);
    cudaGetSymbolAddress((void**)&bc,     g_bc);
    cudaGetSymbolAddress((void**)&rowptr, g_rowptr);
    cudaGetSymbolAddress((void**)&esrc,   g_esrc);
    cudaGetSymbolAddress((void**)&t16,    g_t16);
    cudaGetSymbolAddress((void**)&a16,    g_a16);
    cudaGetSymbolAddress((void**)&b16,    g_b16);
    cudaGetSymbolAddress((void**)&w16,    g_w16);

    auto cdiv = [](long long a, long long b) { return (int)((a + b - 1) / b); };

    // 0: fused prep (CSR + dis + weight images + Wc/bc + xconv + zero d_out)
    k_prep<<<PREP_BLOCKS, PREP_THREADS>>>(src, dst, e, n, (float*)d_out, out_size / 4,
                                          x, W_emb, W1, W2, W3, b_emb, a16);
    // 1: layer-1 GEMM (folded embedding)  t16 = fp16((x@Wc + bc) * dis)
    k_mgemm<128, true, true><<<cdiv(n, 128), 256>>>(
        a16, w16 + 0 * 8192, bc, dis, t16, n);
    // 2: layer-1 agg -> fp16 (B set)
    k_agg<128, true><<<cdiv(n, 8), 256>>>(t16, rowptr, esrc, dis, b1, b16,
                                          nullptr, nullptr, n);
    // 3: layer-2 GEMM   (<- profiled slot)
    k_mgemm<128, true, false><<<cdiv(n, 128), 256>>>(
        b16, w16 + 2 * 8192, nullptr, dis, t16, n);
    // 4: layer-2 agg
    k_agg<128, true><<<cdiv(n, 8), 256>>>(t16, rowptr, esrc, dis, b2, a16,
                                          nullptr, nullptr, n);
    // 5: layer-3 GEMM (BN = 64)
    k_mgemm<64, true, false><<<cdiv(n, 128), 256>>>(
        a16, w16 + 3 * 8192, nullptr, dis, t16, n);
    // 6: layer-3 agg + fused pool
    k_agg<64, false><<<cdiv(n, 8), 256>>>(t16, rowptr, esrc, dis, b3, nullptr,
                                          batch, (float*)d_out, n);
}